// round 10
// baseline (speedup 1.0000x reference)
#include <cuda_runtime.h>
#include <cuda_bf16.h>
#include <cstddef>
#include <cstdint>

#define D 256
#define N_MAX 100000
#define E_MAX 1600000
#define SCAN_BLK 1024

// NOTE (R8 lesson): harness PTX targets compute_103 (no 'a') -> tcgen05/kind::f16
// are ptxas-rejected. Legacy mma.sync is the only tensor path available here.

// ---- scratch (__device__ globals; allocation-free rule) ----
__device__ uint32_t g_feat_hi[(size_t)N_MAX * 128];  // bf16x2 words, [row][128]
__device__ uint32_t g_feat_lo[(size_t)N_MAX * 128];
__device__ uint32_t g_a1_hi[(size_t)N_MAX * 128];
__device__ uint32_t g_a1_lo[(size_t)N_MAX * 128];
__device__ uint32_t g_nhi[(size_t)N_MAX * 128];
__device__ uint32_t g_nlo[(size_t)N_MAX * 128];
__device__ uint32_t g_wthi[2][256 * 256];            // W^T: [n][512k as 256 words]
__device__ uint32_t g_wtlo[2][256 * 256];
__device__ int g_cnt[N_MAX];
__device__ int g_off[N_MAX + 1];
__device__ int g_cursor[N_MAX];
__device__ int g_bsum[(N_MAX + SCAN_BLK - 1) / SCAN_BLK + 1];
__device__ int g_esrc[E_MAX];

// ---- bf16 split helpers ----
__device__ __forceinline__ void split1(float x, float& h, float& l) {
    h = __bfloat162float(__float2bfloat16(x));
    l = x - h;
}
__device__ __forceinline__ uint32_t pack2(float lo_elem, float hi_elem) {
    __nv_bfloat162 t = __floats2bfloat162_rn(lo_elem, hi_elem);
    return *reinterpret_cast<uint32_t*>(&t);
}
__device__ __forceinline__ void split4(float4 v, uint32_t* hw, uint32_t* lw) {
    float h0, l0, h1, l1, h2, l2, h3, l3;
    split1(v.x, h0, l0); split1(v.y, h1, l1);
    split1(v.z, h2, l2); split1(v.w, h3, l3);
    hw[0] = pack2(h0, h1); hw[1] = pack2(h2, h3);
    lw[0] = pack2(l0, l1); lw[1] = pack2(l2, l3);
}

// ---------------------------------------------------------------------------
__global__ void zero_cnt_kernel(int n) {
    int i = blockIdx.x * blockDim.x + threadIdx.x;
    if (i < n) g_cnt[i] = 0;
}

__global__ void copy_convert_kernel(const float* __restrict__ in,
                                    float* __restrict__ out, int n4) {
    int i = blockIdx.x * blockDim.x + threadIdx.x;
    if (i >= n4) return;
    float4 v = ((const float4*)in)[i];
    ((float4*)out)[i] = v;
    uint32_t hw[2], lw[2];
    split4(v, hw, lw);
    *(uint2*)&g_feat_hi[(size_t)i * 2] = make_uint2(hw[0], hw[1]);
    *(uint2*)&g_feat_lo[(size_t)i * 2] = make_uint2(lw[0], lw[1]);
}

__global__ void hist_kernel(const int* __restrict__ dst, int E) {
    int i = blockIdx.x * blockDim.x + threadIdx.x;
    if (i < E) atomicAdd(&g_cnt[dst[i]], 1);
}

__global__ void scan_blocks_kernel(int n) {
    __shared__ int sm[SCAN_BLK];
    int tid = threadIdx.x;
    int i = blockIdx.x * SCAN_BLK + tid;
    int v = (i < n) ? g_cnt[i] : 0;
    sm[tid] = v;
    __syncthreads();
#pragma unroll
    for (int off = 1; off < SCAN_BLK; off <<= 1) {
        int t = (tid >= off) ? sm[tid - off] : 0;
        __syncthreads();
        sm[tid] += t;
        __syncthreads();
    }
    if (i < n) g_off[i] = sm[tid] - v;
    if (tid == SCAN_BLK - 1) g_bsum[blockIdx.x] = sm[tid];
}

__global__ void scan_add_kernel(int n, int E) {
    __shared__ int pref;
    int g = (blockIdx.x * 256) >> 10;
    if (threadIdx.x < 32) {
        int s = 0;
        for (int j = threadIdx.x; j < g; j += 32) s += g_bsum[j];
#pragma unroll
        for (int o = 16; o; o >>= 1) s += __shfl_down_sync(0xFFFFFFFFu, s, o);
        if (threadIdx.x == 0) pref = s;
    }
    __syncthreads();
    int i = blockIdx.x * 256 + threadIdx.x;
    if (i < n) {
        int v = g_off[i] + pref;
        g_off[i] = v;
        g_cursor[i] = v;
    }
    if (i == 0) g_off[n] = E;
}

__global__ void fill_kernel(const int* __restrict__ src,
                            const int* __restrict__ dst, int E) {
    int e = blockIdx.x * blockDim.x + threadIdx.x;
    if (e < E) {
        int d = dst[e];
        int p = atomicAdd(&g_cursor[d], 1);
        g_esrc[p] = src[e];
    }
}

__global__ void wconv_kernel(const float* __restrict__ Ws0, const float* __restrict__ Wn0,
                             const float* __restrict__ Ws1, const float* __restrict__ Wn1) {
    int idx = blockIdx.x * blockDim.x + threadIdx.x;
    if (idx >= 256 * 256) return;
    int layer = blockIdx.y;
    const float* Ws = layer ? Ws1 : Ws0;
    const float* Wn = layer ? Wn1 : Wn0;
    int n = idx & 255;
    int wp = idx >> 8;
    int k0 = wp * 2, k1 = k0 + 1;
    float v0 = (k0 < 256) ? Ws[k0 * 256 + n] : Wn[(k0 - 256) * 256 + n];
    float v1 = (k1 < 256) ? Ws[k1 * 256 + n] : Wn[(k1 - 256) * 256 + n];
    float h0, l0, h1, l1;
    split1(v0, h0, l0);
    split1(v1, h1, l1);
    g_wthi[layer][n * 256 + wp] = pack2(h0, h1);
    g_wtlo[layer][n * 256 + wp] = pack2(l0, l1);
}

// ---------------------------------------------------------------------------
__global__ void gather_kernel(const float* __restrict__ X, int N) {
    int node = blockIdx.x * 8 + (threadIdx.x >> 5);
    if (node >= N) return;
    int lane = threadIdx.x & 31;

    int beg = g_off[node];
    int end = g_off[node + 1];

    float4 a0 = make_float4(0.f, 0.f, 0.f, 0.f);
    float4 a1 = make_float4(0.f, 0.f, 0.f, 0.f);

    int i = beg;
    for (; i + 1 < end; i += 2) {
        int s0 = __ldg(g_esrc + i);
        int s1 = __ldg(g_esrc + i + 1);
        const float4* x0 = (const float4*)(X + (size_t)s0 * D);
        const float4* x1 = (const float4*)(X + (size_t)s1 * D);
        float4 v00 = __ldg(x0 + lane);
        float4 v01 = __ldg(x0 + lane + 32);
        float4 v10 = __ldg(x1 + lane);
        float4 v11 = __ldg(x1 + lane + 32);
        a0.x += v00.x + v10.x; a0.y += v00.y + v10.y;
        a0.z += v00.z + v10.z; a0.w += v00.w + v10.w;
        a1.x += v01.x + v11.x; a1.y += v01.y + v11.y;
        a1.z += v01.z + v11.z; a1.w += v01.w + v11.w;
    }
    if (i < end) {
        int s0 = __ldg(g_esrc + i);
        const float4* x0 = (const float4*)(X + (size_t)s0 * D);
        float4 v00 = __ldg(x0 + lane);
        float4 v01 = __ldg(x0 + lane + 32);
        a0.x += v00.x; a0.y += v00.y; a0.z += v00.z; a0.w += v00.w;
        a1.x += v01.x; a1.y += v01.y; a1.z += v01.z; a1.w += v01.w;
    }

    float inv = (end > beg) ? (1.0f / (float)(end - beg)) : 0.f;
    a0.x *= inv; a0.y *= inv; a0.z *= inv; a0.w *= inv;
    a1.x *= inv; a1.y *= inv; a1.z *= inv; a1.w *= inv;

    uint32_t hw[2], lw[2];
    size_t base = (size_t)node * 128;
    split4(a0, hw, lw);
    *(uint2*)&g_nhi[base + lane * 2] = make_uint2(hw[0], hw[1]);
    *(uint2*)&g_nlo[base + lane * 2] = make_uint2(lw[0], lw[1]);
    split4(a1, hw, lw);
    *(uint2*)&g_nhi[base + 64 + lane * 2] = make_uint2(hw[0], hw[1]);
    *(uint2*)&g_nlo[base + 64 + lane * 2] = make_uint2(lw[0], lw[1]);
}

// ---------------------------------------------------------------------------
// Split-BF16 half-GEMM (K=256), CTA tile 128x128, warp tile 32x64.
// neigh_mode=0: out = A_self @ W_self-half (raw partial, no bias)
// neigh_mode=1: out += NH @ W_neigh-half + bias (+relu/split if layer 0)
#define T_STR 20
#define SA_SZ (128 * T_STR)
#define SB_SZ (128 * T_STR)
#define SMEM_WORDS (2 * (2 * SA_SZ + 2 * SB_SZ))
#define SMEM_BYTES (SMEM_WORDS * 4)

__device__ __forceinline__ void cp_async16(void* s, const void* g, bool pred) {
    uint32_t sa = (uint32_t)__cvta_generic_to_shared(s);
    int sz = pred ? 16 : 0;
    asm volatile("cp.async.cg.shared.global [%0], [%1], 16, %2;"
                 :: "r"(sa), "l"(g), "r"(sz) : "memory");
}

__device__ __forceinline__ void mma_bf16(float* c, const uint32_t* a, const uint32_t* b) {
    asm volatile(
        "mma.sync.aligned.m16n8k16.row.col.f32.bf16.bf16.f32 "
        "{%0,%1,%2,%3}, {%4,%5,%6,%7}, {%8,%9}, {%0,%1,%2,%3};"
        : "+f"(c[0]), "+f"(c[1]), "+f"(c[2]), "+f"(c[3])
        : "r"(a[0]), "r"(a[1]), "r"(a[2]), "r"(a[3]), "r"(b[0]), "r"(b[1]));
}

__device__ __forceinline__ void ldsm_x4(uint32_t* r, uint32_t addr) {
    asm volatile("ldmatrix.sync.aligned.m8n8.x4.shared.b16 {%0,%1,%2,%3}, [%4];"
                 : "=r"(r[0]), "=r"(r[1]), "=r"(r[2]), "=r"(r[3]) : "r"(addr));
}

__global__ void __launch_bounds__(256) sage_gemm_kernel(
    const float* __restrict__ bias,
    float* __restrict__ out,
    int M, int layer, int neigh_mode) {
    extern __shared__ uint32_t smem[];
    uint32_t* sAh = smem;
    uint32_t* sAl = smem + 2 * SA_SZ;
    uint32_t* sBh = smem + 4 * SA_SZ;
    uint32_t* sBl = smem + 4 * SA_SZ + 2 * SB_SZ;
    const uint32_t smem_u32 = (uint32_t)__cvta_generic_to_shared(smem);

    const int tid = threadIdx.x;
    const int lane = tid & 31;
    const int wid = tid >> 5;
    const int wm = wid >> 1;
    const int wn = wid & 1;
    const int bm = blockIdx.y * 128;
    const int bn = blockIdx.x * 128;

    const uint32_t* Ah;
    const uint32_t* Al;
    if (neigh_mode) { Ah = g_nhi; Al = g_nlo; }
    else if (layer) { Ah = g_a1_hi; Al = g_a1_lo; }
    else            { Ah = g_feat_hi; Al = g_feat_lo; }
    const uint32_t* Whi = g_wthi[layer];
    const uint32_t* Wlo = g_wtlo[layer];
    const int wb = neigh_mode ? 128 : 0;   // word offset into Wt rows

    float acc[2][8][4] = {};

    auto load_tile = [&](int it, int buf) {
        int klw = it * 16;
        uint32_t* dAh = sAh + buf * SA_SZ;
        uint32_t* dAl = sAl + buf * SA_SZ;
        uint32_t* dBh = sBh + buf * SB_SZ;
        uint32_t* dBl = sBl + buf * SB_SZ;
#pragma unroll
        for (int i = 0; i < 2; ++i) {            // A: 128 rows x 4 chunks
            int ci = i * 256 + tid;
            int row = ci >> 2, ch = ci & 3;
            int grow = bm + row;
            bool ok = grow < M;
            size_t off = (size_t)(ok ? grow : (M - 1)) * 128 + klw + ch * 4;
            cp_async16(dAh + row * T_STR + ch * 4, Ah + off, ok);
            cp_async16(dAl + row * T_STR + ch * 4, Al + off, ok);
        }
#pragma unroll
        for (int i = 0; i < 2; ++i) {            // B: 128 rows x 4 chunks
            int ci = i * 256 + tid;
            int row = ci >> 2, ch = ci & 3;
            size_t off = (size_t)(bn + row) * 256 + wb + it * 16 + ch * 4;
            cp_async16(dBh + row * T_STR + ch * 4, Whi + off, true);
            cp_async16(dBl + row * T_STR + ch * 4, Wlo + off, true);
        }
    };

    load_tile(0, 0);
    asm volatile("cp.async.commit_group;" ::: "memory");

    const int a_r = wm * 32 + (lane & 15);
    const int a_w = (lane >> 4) << 2;
    const int b_r = wn * 64 + (lane & 7) + ((lane >> 4) << 3);
    const int b_w = ((lane >> 3) & 1) << 2;

    const int K_ITERS = 256 / 32;  // 8
#pragma unroll 1
    for (int it = 0; it < K_ITERS; ++it) {
        if (it + 1 < K_ITERS) {
            load_tile(it + 1, (it + 1) & 1);
            asm volatile("cp.async.commit_group;" ::: "memory");
            asm volatile("cp.async.wait_group 1;" ::: "memory");
        } else {
            asm volatile("cp.async.wait_group 0;" ::: "memory");
        }
        __syncthreads();

        const uint32_t aHb = smem_u32 + ((it & 1) * SA_SZ) * 4;
        const uint32_t aLb = aHb + (2 * SA_SZ) * 4;
        const uint32_t bHb = smem_u32 + (4 * SA_SZ + (it & 1) * SB_SZ) * 4;
        const uint32_t bLb = bHb + (2 * SB_SZ) * 4;

#pragma unroll
        for (int ks = 0; ks < 2; ++ks) {
            uint32_t ah[2][4], al[2][4], bh[8][2], bl[8][2];
#pragma unroll
            for (int mt = 0; mt < 2; ++mt) {
                uint32_t off = (uint32_t)(((a_r + mt * 16) * T_STR + a_w + ks * 8) * 4);
                ldsm_x4(ah[mt], aHb + off);
                ldsm_x4(al[mt], aLb + off);
            }
#pragma unroll
            for (int np = 0; np < 4; ++np) {
                uint32_t off = (uint32_t)(((b_r + np * 16) * T_STR + b_w + ks * 8) * 4);
                uint32_t t[4];
                ldsm_x4(t, bHb + off);
                bh[np * 2][0] = t[0]; bh[np * 2][1] = t[1];
                bh[np * 2 + 1][0] = t[2]; bh[np * 2 + 1][1] = t[3];
                ldsm_x4(t, bLb + off);
                bl[np * 2][0] = t[0]; bl[np * 2][1] = t[1];
                bl[np * 2 + 1][0] = t[2]; bl[np * 2 + 1][1] = t[3];
            }
#pragma unroll
            for (int mt = 0; mt < 2; ++mt)
#pragma unroll
                for (int nt = 0; nt < 8; ++nt) {
                    mma_bf16(acc[mt][nt], ah[mt], bl[nt]);
                    mma_bf16(acc[mt][nt], al[mt], bh[nt]);
                    mma_bf16(acc[mt][nt], ah[mt], bh[nt]);
                }
        }
        __syncthreads();
    }

    const int do_final = neigh_mode;
    const int do_relu = (neigh_mode && layer == 0);

#pragma unroll
    for (int mt = 0; mt < 2; ++mt) {
        int r0 = bm + wm * 32 + mt * 16 + (lane >> 2);
#pragma unroll
        for (int nt = 0; nt < 8; ++nt) {
            int cc = bn + wn * 64 + nt * 8 + (lane & 3) * 2;
            float2 v0, v1;
            v0.x = acc[mt][nt][0]; v0.y = acc[mt][nt][1];
            v1.x = acc[mt][nt][2]; v1.y = acc[mt][nt][3];
            if (do_final) {
                float bx = __ldg(bias + cc);
                float by = __ldg(bias + cc + 1);
                if (r0 < M) {
                    float2 p = *(const float2*)(out + (size_t)r0 * 256 + cc);
                    v0.x += p.x + bx; v0.y += p.y + by;
                }
                if (r0 + 8 < M) {
                    float2 p = *(const float2*)(out + (size_t)(r0 + 8) * 256 + cc);
                    v1.x += p.x + bx; v1.y += p.y + by;
                }
                if (do_relu) {
                    v0.x = fmaxf(v0.x, 0.f); v0.y = fmaxf(v0.y, 0.f);
                    v1.x = fmaxf(v1.x, 0.f); v1.y = fmaxf(v1.y, 0.f);
                }
            }
            if (r0 < M) {
                *(float2*)(out + (size_t)r0 * 256 + cc) = v0;
                if (do_relu) {
                    float h0, l0, h1, l1;
                    split1(v0.x, h0, l0); split1(v0.y, h1, l1);
                    g_a1_hi[(size_t)r0 * 128 + (cc >> 1)] = pack2(h0, h1);
                    g_a1_lo[(size_t)r0 * 128 + (cc >> 1)] = pack2(l0, l1);
                }
            }
            if (r0 + 8 < M) {
                *(float2*)(out + (size_t)(r0 + 8) * 256 + cc) = v1;
                if (do_relu) {
                    float h0, l0, h1, l1;
                    split1(v1.x, h0, l0); split1(v1.y, h1, l1);
                    g_a1_hi[(size_t)(r0 + 8) * 128 + (cc >> 1)] = pack2(h0, h1);
                    g_a1_lo[(size_t)(r0 + 8) * 128 + (cc >> 1)] = pack2(l0, l1);
                }
            }
        }
    }
}

// ---------------------------------------------------------------------------
extern "C" void kernel_launch(void* const* d_in, const int* in_sizes, int n_in,
                              void* d_out, int out_size) {
    const float* feat = (const float*)d_in[0];
    const int*   src  = (const int*)d_in[1];
    const int*   dst  = (const int*)d_in[2];
    const float* Ws0  = (const float*)d_in[3];
    const float* Wn0  = (const float*)d_in[4];
    const float* b0   = (const float*)d_in[5];
    const float* Ws1  = (const float*)d_in[6];
    const float* Wn1  = (const float*)d_in[7];
    const float* b1   = (const float*)d_in[8];

    int N = in_sizes[0] / D;   // 100000
    int E = in_sizes[1];       // 1600000

    float* out0 = (float*)d_out;
    float* a1   = out0 + (size_t)N * D;
    float* h2   = out0 + 2 * (size_t)N * D;

    int nd4 = N * (D / 4);
    int nb = (N + SCAN_BLK - 1) / SCAN_BLK;
    dim3 ggrid(2, (N + 127) / 128);

    cudaFuncSetAttribute(sage_gemm_kernel,
                         cudaFuncAttributeMaxDynamicSharedMemorySize, SMEM_BYTES);

    // Fork a secondary branch (stream + events created fresh each call;
    // handles are intentionally leaked — destroying mid-capture is unsafe,
    // and the harness only invokes this a handful of times).
    cudaStream_t s1;
    cudaStreamCreateWithFlags(&s1, cudaStreamNonBlocking);
    cudaEvent_t eFork, eJoin1, eMid, eJoin2;
    cudaEventCreateWithFlags(&eFork,  cudaEventDisableTiming);
    cudaEventCreateWithFlags(&eJoin1, cudaEventDisableTiming);
    cudaEventCreateWithFlags(&eMid,   cudaEventDisableTiming);
    cudaEventCreateWithFlags(&eJoin2, cudaEventDisableTiming);

    cudaEventRecord(eFork, 0);
    cudaStreamWaitEvent(s1, eFork, 0);

    // --- branch s1: feature/weight conversion + self-half of layer 1 ---
    copy_convert_kernel<<<(nd4 + 255) / 256, 256, 0, s1>>>(feat, out0, nd4);
    wconv_kernel<<<dim3((256 * 256 + 255) / 256, 2), 256, 0, s1>>>(Ws0, Wn0, Ws1, Wn1);
    sage_gemm_kernel<<<ggrid, 256, SMEM_BYTES, s1>>>(b0, a1, N, 0, 0);  // self L0
    cudaEventRecord(eJoin1, s1);

    // --- branch s0: CSR build + gather layer 1 ---
    zero_cnt_kernel<<<(N + 255) / 256, 256>>>(N);
    hist_kernel<<<(E + 255) / 256, 256>>>(dst, E);
    scan_blocks_kernel<<<nb, SCAN_BLK>>>(N);
    scan_add_kernel<<<(N + 255) / 256, 256>>>(N, E);
    fill_kernel<<<(E + 255) / 256, 256>>>(src, dst, E);
    gather_kernel<<<(N + 7) / 8, 256>>>(feat, N);

    // join: neigh-half of layer 1 (finalizes a1: += neigh + b0, relu, split)
    cudaStreamWaitEvent(0, eJoin1, 0);
    sage_gemm_kernel<<<ggrid, 256, SMEM_BYTES>>>(b0, a1, N, 0, 1);      // neigh L0

    // fork again after a1 is final
    cudaEventRecord(eMid, 0);
    cudaStreamWaitEvent(s1, eMid, 0);

    // --- branch s1: self-half of layer 2 (tensor-bound) ---
    sage_gemm_kernel<<<ggrid, 256, SMEM_BYTES, s1>>>(b1, h2, N, 1, 0);  // self L1
    cudaEventRecord(eJoin2, s1);

    // --- branch s0: gather layer 2 (L2-bound; overlaps with self L1) ---
    gather_kernel<<<(N + 7) / 8, 256>>>(a1, N);

    // join: neigh-half of layer 2 (finalizes h2)
    cudaStreamWaitEvent(0, eJoin2, 0);
    sage_gemm_kernel<<<ggrid, 256, SMEM_BYTES>>>(b1, h2, N, 1, 1);      // neigh L1
}

// round 11
// speedup vs baseline: 1.0654x; 1.0654x over previous
#include <cuda_runtime.h>
#include <cuda_bf16.h>
#include <cstddef>
#include <cstdint>

#define D 256
#define N_MAX 100000
#define E_MAX 1600000
#define SCAN_BLK 1024

// R8 lesson: harness PTX targets compute_103 (no 'a') -> tcgen05 unavailable.
// R10 lesson: all kernels saturate the chip -> stream overlap buys nothing;
// keep single stream, optimize per-kernel efficiency.

// ---- scratch (__device__ globals; allocation-free rule) ----
__device__ uint32_t g_feat_hi[(size_t)N_MAX * 128];  // bf16x2 words, [row][128]
__device__ uint32_t g_feat_lo[(size_t)N_MAX * 128];
__device__ uint32_t g_a1_hi[(size_t)N_MAX * 128];
__device__ uint32_t g_a1_lo[(size_t)N_MAX * 128];
__device__ uint32_t g_nhi[(size_t)N_MAX * 128];
__device__ uint32_t g_nlo[(size_t)N_MAX * 128];
__device__ uint32_t g_wthi[2][256 * 256];            // W^T: [n][512k as 256 words]
__device__ uint32_t g_wtlo[2][256 * 256];
__device__ int g_cnt[N_MAX];
__device__ int g_off[N_MAX + 1];
__device__ int g_cursor[N_MAX];
__device__ int g_bsum[(N_MAX + SCAN_BLK - 1) / SCAN_BLK + 1];
__device__ int g_esrc[E_MAX];

// ---- bf16 split helpers ----
__device__ __forceinline__ void split1(float x, float& h, float& l) {
    h = __bfloat162float(__float2bfloat16(x));
    l = x - h;
}
__device__ __forceinline__ uint32_t pack2(float lo_elem, float hi_elem) {
    __nv_bfloat162 t = __floats2bfloat162_rn(lo_elem, hi_elem);
    return *reinterpret_cast<uint32_t*>(&t);
}
__device__ __forceinline__ void split4(float4 v, uint32_t* hw, uint32_t* lw) {
    float h0, l0, h1, l1, h2, l2, h3, l3;
    split1(v.x, h0, l0); split1(v.y, h1, l1);
    split1(v.z, h2, l2); split1(v.w, h3, l3);
    hw[0] = pack2(h0, h1); hw[1] = pack2(h2, h3);
    lw[0] = pack2(l0, l1); lw[1] = pack2(l2, l3);
}

// ---------------------------------------------------------------------------
// copy feat -> out[0], split to g_feat_hi/lo, AND zero g_cnt (fused)
__global__ void copy_convert_kernel(const float* __restrict__ in,
                                    float* __restrict__ out, int n4, int N) {
    int i = blockIdx.x * blockDim.x + threadIdx.x;
    if (i < N) g_cnt[i] = 0;
    if (i >= n4) return;
    float4 v = ((const float4*)in)[i];
    ((float4*)out)[i] = v;
    uint32_t hw[2], lw[2];
    split4(v, hw, lw);
    *(uint2*)&g_feat_hi[(size_t)i * 2] = make_uint2(hw[0], hw[1]);
    *(uint2*)&g_feat_lo[(size_t)i * 2] = make_uint2(lw[0], lw[1]);
}

__global__ void hist_kernel(const int* __restrict__ dst, int E) {
    int i = blockIdx.x * blockDim.x + threadIdx.x;
    if (i < E) atomicAdd(&g_cnt[dst[i]], 1);
}

__global__ void scan_blocks_kernel(int n) {
    __shared__ int sm[SCAN_BLK];
    int tid = threadIdx.x;
    int i = blockIdx.x * SCAN_BLK + tid;
    int v = (i < n) ? g_cnt[i] : 0;
    sm[tid] = v;
    __syncthreads();
#pragma unroll
    for (int off = 1; off < SCAN_BLK; off <<= 1) {
        int t = (tid >= off) ? sm[tid - off] : 0;
        __syncthreads();
        sm[tid] += t;
        __syncthreads();
    }
    if (i < n) g_off[i] = sm[tid] - v;
    if (tid == SCAN_BLK - 1) g_bsum[blockIdx.x] = sm[tid];
}

__global__ void scan_add_kernel(int n, int E) {
    __shared__ int pref;
    int g = (blockIdx.x * 256) >> 10;
    if (threadIdx.x < 32) {
        int s = 0;
        for (int j = threadIdx.x; j < g; j += 32) s += g_bsum[j];
#pragma unroll
        for (int o = 16; o; o >>= 1) s += __shfl_down_sync(0xFFFFFFFFu, s, o);
        if (threadIdx.x == 0) pref = s;
    }
    __syncthreads();
    int i = blockIdx.x * 256 + threadIdx.x;
    if (i < n) {
        int v = g_off[i] + pref;
        g_off[i] = v;
        g_cursor[i] = v;
    }
    if (i == 0) g_off[n] = E;
}

__global__ void fill_kernel(const int* __restrict__ src,
                            const int* __restrict__ dst, int E) {
    int e = blockIdx.x * blockDim.x + threadIdx.x;
    if (e < E) {
        int d = dst[e];
        int p = atomicAdd(&g_cursor[d], 1);
        g_esrc[p] = src[e];
    }
}

__global__ void wconv_kernel(const float* __restrict__ Ws0, const float* __restrict__ Wn0,
                             const float* __restrict__ Ws1, const float* __restrict__ Wn1) {
    int idx = blockIdx.x * blockDim.x + threadIdx.x;
    if (idx >= 256 * 256) return;
    int layer = blockIdx.y;
    const float* Ws = layer ? Ws1 : Ws0;
    const float* Wn = layer ? Wn1 : Wn0;
    int n = idx & 255;
    int wp = idx >> 8;
    int k0 = wp * 2, k1 = k0 + 1;
    float v0 = (k0 < 256) ? Ws[k0 * 256 + n] : Wn[(k0 - 256) * 256 + n];
    float v1 = (k1 < 256) ? Ws[k1 * 256 + n] : Wn[(k1 - 256) * 256 + n];
    float h0, l0, h1, l1;
    split1(v0, h0, l0);
    split1(v1, h1, l1);
    g_wthi[layer][n * 256 + wp] = pack2(h0, h1);
    g_wtlo[layer][n * 256 + wp] = pack2(l0, l1);
}

// ---------------------------------------------------------------------------
// Gather aggregation: one warp per dst node; 4-edge unroll (8 float4s in flight).
__global__ void gather_kernel(const float* __restrict__ X, int N) {
    int node = blockIdx.x * 8 + (threadIdx.x >> 5);
    if (node >= N) return;
    int lane = threadIdx.x & 31;

    int beg = g_off[node];
    int end = g_off[node + 1];

    float4 a0 = make_float4(0.f, 0.f, 0.f, 0.f);
    float4 a1 = make_float4(0.f, 0.f, 0.f, 0.f);

    int i = beg;
    for (; i + 3 < end; i += 4) {
        int s0 = __ldg(g_esrc + i);
        int s1 = __ldg(g_esrc + i + 1);
        int s2 = __ldg(g_esrc + i + 2);
        int s3 = __ldg(g_esrc + i + 3);
        const float4* x0 = (const float4*)(X + (size_t)s0 * D);
        const float4* x1 = (const float4*)(X + (size_t)s1 * D);
        const float4* x2 = (const float4*)(X + (size_t)s2 * D);
        const float4* x3 = (const float4*)(X + (size_t)s3 * D);
        float4 v00 = __ldg(x0 + lane), v01 = __ldg(x0 + lane + 32);
        float4 v10 = __ldg(x1 + lane), v11 = __ldg(x1 + lane + 32);
        float4 v20 = __ldg(x2 + lane), v21 = __ldg(x2 + lane + 32);
        float4 v30 = __ldg(x3 + lane), v31 = __ldg(x3 + lane + 32);
        a0.x += (v00.x + v10.x) + (v20.x + v30.x);
        a0.y += (v00.y + v10.y) + (v20.y + v30.y);
        a0.z += (v00.z + v10.z) + (v20.z + v30.z);
        a0.w += (v00.w + v10.w) + (v20.w + v30.w);
        a1.x += (v01.x + v11.x) + (v21.x + v31.x);
        a1.y += (v01.y + v11.y) + (v21.y + v31.y);
        a1.z += (v01.z + v11.z) + (v21.z + v31.z);
        a1.w += (v01.w + v11.w) + (v21.w + v31.w);
    }
    for (; i < end; ++i) {
        int s0 = __ldg(g_esrc + i);
        const float4* x0 = (const float4*)(X + (size_t)s0 * D);
        float4 v00 = __ldg(x0 + lane);
        float4 v01 = __ldg(x0 + lane + 32);
        a0.x += v00.x; a0.y += v00.y; a0.z += v00.z; a0.w += v00.w;
        a1.x += v01.x; a1.y += v01.y; a1.z += v01.z; a1.w += v01.w;
    }

    float inv = (end > beg) ? (1.0f / (float)(end - beg)) : 0.f;
    a0.x *= inv; a0.y *= inv; a0.z *= inv; a0.w *= inv;
    a1.x *= inv; a1.y *= inv; a1.z *= inv; a1.w *= inv;

    uint32_t hw[2], lw[2];
    size_t base = (size_t)node * 128;
    split4(a0, hw, lw);
    *(uint2*)&g_nhi[base + lane * 2] = make_uint2(hw[0], hw[1]);
    *(uint2*)&g_nlo[base + lane * 2] = make_uint2(lw[0], lw[1]);
    split4(a1, hw, lw);
    *(uint2*)&g_nhi[base + 64 + lane * 2] = make_uint2(hw[0], hw[1]);
    *(uint2*)&g_nlo[base + 64 + lane * 2] = make_uint2(lw[0], lw[1]);
}

// ---------------------------------------------------------------------------
// Split-BF16 tensor GEMM (ldmatrix), CTA 128x128, warp 32x64, fused K=512.
// Register-lean: B fragments staged on demand (8 live regs) so 2 CTAs/SM fit.
#define T_STR 20
#define SA_SZ (128 * T_STR)
#define SB_SZ (128 * T_STR)
#define SMEM_WORDS (2 * (2 * SA_SZ + 2 * SB_SZ))
#define SMEM_BYTES (SMEM_WORDS * 4)

__device__ __forceinline__ void cp_async16(void* s, const void* g, bool pred) {
    uint32_t sa = (uint32_t)__cvta_generic_to_shared(s);
    int sz = pred ? 16 : 0;
    asm volatile("cp.async.cg.shared.global [%0], [%1], 16, %2;"
                 :: "r"(sa), "l"(g), "r"(sz) : "memory");
}

__device__ __forceinline__ void mma_bf16(float* c, const uint32_t* a, const uint32_t* b) {
    asm volatile(
        "mma.sync.aligned.m16n8k16.row.col.f32.bf16.bf16.f32 "
        "{%0,%1,%2,%3}, {%4,%5,%6,%7}, {%8,%9}, {%0,%1,%2,%3};"
        : "+f"(c[0]), "+f"(c[1]), "+f"(c[2]), "+f"(c[3])
        : "r"(a[0]), "r"(a[1]), "r"(a[2]), "r"(a[3]), "r"(b[0]), "r"(b[1]));
}

__device__ __forceinline__ void ldsm_x4(uint32_t* r, uint32_t addr) {
    asm volatile("ldmatrix.sync.aligned.m8n8.x4.shared.b16 {%0,%1,%2,%3}, [%4];"
                 : "=r"(r[0]), "=r"(r[1]), "=r"(r[2]), "=r"(r[3]) : "r"(addr));
}

__global__ void __launch_bounds__(256, 2) sage_gemm_kernel(
    const float* __restrict__ bias,
    float* __restrict__ out,
    int M, int layer, int do_relu) {
    extern __shared__ uint32_t smem[];
    uint32_t* sAh = smem;
    uint32_t* sAl = smem + 2 * SA_SZ;
    uint32_t* sBh = smem + 4 * SA_SZ;
    uint32_t* sBl = smem + 4 * SA_SZ + 2 * SB_SZ;
    const uint32_t smem_u32 = (uint32_t)__cvta_generic_to_shared(smem);

    const int tid = threadIdx.x;
    const int lane = tid & 31;
    const int wid = tid >> 5;
    const int wm = wid >> 1;          // 0..3  (m32 each)
    const int wn = wid & 1;           // 0..1  (n64 each)
    const int bm = blockIdx.y * 128;
    const int bn = blockIdx.x * 128;

    const uint32_t* Xhi = layer ? g_a1_hi : g_feat_hi;
    const uint32_t* Xlo = layer ? g_a1_lo : g_feat_lo;
    const uint32_t* Whi = g_wthi[layer];
    const uint32_t* Wlo = g_wtlo[layer];

    float acc[2][8][4] = {};

    auto load_tile = [&](int it, int buf) {
        int kg = it * 32;
        const uint32_t* Ah = (kg < 256) ? Xhi : (const uint32_t*)g_nhi;
        const uint32_t* Al = (kg < 256) ? Xlo : (const uint32_t*)g_nlo;
        int klw = (kg & 255) >> 1;
        uint32_t* dAh = sAh + buf * SA_SZ;
        uint32_t* dAl = sAl + buf * SA_SZ;
        uint32_t* dBh = sBh + buf * SB_SZ;
        uint32_t* dBl = sBl + buf * SB_SZ;
#pragma unroll
        for (int i = 0; i < 2; ++i) {            // A: 128 rows x 4 chunks
            int ci = i * 256 + tid;
            int row = ci >> 2, ch = ci & 3;
            int grow = bm + row;
            bool ok = grow < M;
            size_t off = (size_t)(ok ? grow : (M - 1)) * 128 + klw + ch * 4;
            cp_async16(dAh + row * T_STR + ch * 4, Ah + off, ok);
            cp_async16(dAl + row * T_STR + ch * 4, Al + off, ok);
        }
#pragma unroll
        for (int i = 0; i < 2; ++i) {            // B: 128 rows x 4 chunks
            int ci = i * 256 + tid;
            int row = ci >> 2, ch = ci & 3;
            size_t off = (size_t)(bn + row) * 256 + it * 16 + ch * 4;
            cp_async16(dBh + row * T_STR + ch * 4, Whi + off, true);
            cp_async16(dBl + row * T_STR + ch * 4, Wlo + off, true);
        }
    };

    load_tile(0, 0);
    asm volatile("cp.async.commit_group;" ::: "memory");

    const int a_r = wm * 32 + (lane & 15);
    const int a_w = (lane >> 4) << 2;
    const int b_r = wn * 64 + (lane & 7) + ((lane >> 4) << 3);
    const int b_w = ((lane >> 3) & 1) << 2;

    const int K_ITERS = 512 / 32;  // 16
#pragma unroll 1
    for (int it = 0; it < K_ITERS; ++it) {
        if (it + 1 < K_ITERS) {
            load_tile(it + 1, (it + 1) & 1);
            asm volatile("cp.async.commit_group;" ::: "memory");
            asm volatile("cp.async.wait_group 1;" ::: "memory");
        } else {
            asm volatile("cp.async.wait_group 0;" ::: "memory");
        }
        __syncthreads();

        const uint32_t aHb = smem_u32 + ((it & 1) * SA_SZ) * 4;
        const uint32_t aLb = aHb + (2 * SA_SZ) * 4;
        const uint32_t bHb = smem_u32 + (4 * SA_SZ + (it & 1) * SB_SZ) * 4;
        const uint32_t bLb = bHb + (2 * SB_SZ) * 4;

#pragma unroll
        for (int ks = 0; ks < 2; ++ks) {
            uint32_t ah[2][4], al[2][4];
#pragma unroll
            for (int mt = 0; mt < 2; ++mt) {
                uint32_t off = (uint32_t)(((a_r + mt * 16) * T_STR + a_w + ks * 8) * 4);
                ldsm_x4(ah[mt], aHb + off);
                ldsm_x4(al[mt], aLb + off);
            }
            // B fragments staged on demand: only 8 live b-regs at a time.
#pragma unroll
            for (int np = 0; np < 4; ++np) {
                uint32_t off = (uint32_t)(((b_r + np * 16) * T_STR + b_w + ks * 8) * 4);
                uint32_t th[4], tl[4];
                ldsm_x4(th, bHb + off);
                ldsm_x4(tl, bLb + off);
#pragma unroll
                for (int mt = 0; mt < 2; ++mt) {
#pragma unroll
                    for (int sub = 0; sub < 2; ++sub) {
                        float* a = acc[mt][np * 2 + sub];
                        mma_bf16(a, ah[mt], tl + sub * 2);
                        mma_bf16(a, al[mt], th + sub * 2);
                        mma_bf16(a, ah[mt], th + sub * 2);
                    }
                }
            }
        }
        __syncthreads();
    }

    // ---- epilogue: bias (+relu); layer 0 also writes a1 hi/lo bf16 ----
#pragma unroll
    for (int mt = 0; mt < 2; ++mt) {
        int r0 = bm + wm * 32 + mt * 16 + (lane >> 2);
#pragma unroll
        for (int nt = 0; nt < 8; ++nt) {
            int cc = bn + wn * 64 + nt * 8 + (lane & 3) * 2;
            float bx = __ldg(bias + cc);
            float by = __ldg(bias + cc + 1);
            float2 v0, v1;
            v0.x = acc[mt][nt][0] + bx; v0.y = acc[mt][nt][1] + by;
            v1.x = acc[mt][nt][2] + bx; v1.y = acc[mt][nt][3] + by;
            if (do_relu) {
                v0.x = fmaxf(v0.x, 0.f); v0.y = fmaxf(v0.y, 0.f);
                v1.x = fmaxf(v1.x, 0.f); v1.y = fmaxf(v1.y, 0.f);
            }
            if (r0 < M) {
                *(float2*)(out + (size_t)r0 * 256 + cc) = v0;
                if (do_relu) {
                    float h0, l0, h1, l1;
                    split1(v0.x, h0, l0); split1(v0.y, h1, l1);
                    g_a1_hi[(size_t)r0 * 128 + (cc >> 1)] = pack2(h0, h1);
                    g_a1_lo[(size_t)r0 * 128 + (cc >> 1)] = pack2(l0, l1);
                }
            }
            if (r0 + 8 < M) {
                *(float2*)(out + (size_t)(r0 + 8) * 256 + cc) = v1;
                if (do_relu) {
                    float h0, l0, h1, l1;
                    split1(v1.x, h0, l0); split1(v1.y, h1, l1);
                    g_a1_hi[(size_t)(r0 + 8) * 128 + (cc >> 1)] = pack2(h0, h1);
                    g_a1_lo[(size_t)(r0 + 8) * 128 + (cc >> 1)] = pack2(l0, l1);
                }
            }
        }
    }
}

// ---------------------------------------------------------------------------
extern "C" void kernel_launch(void* const* d_in, const int* in_sizes, int n_in,
                              void* d_out, int out_size) {
    const float* feat = (const float*)d_in[0];
    const int*   src  = (const int*)d_in[1];
    const int*   dst  = (const int*)d_in[2];
    const float* Ws0  = (const float*)d_in[3];
    const float* Wn0  = (const float*)d_in[4];
    const float* b0   = (const float*)d_in[5];
    const float* Ws1  = (const float*)d_in[6];
    const float* Wn1  = (const float*)d_in[7];
    const float* b1   = (const float*)d_in[8];

    int N = in_sizes[0] / D;   // 100000
    int E = in_sizes[1];       // 1600000

    float* out0 = (float*)d_out;
    float* a1   = out0 + (size_t)N * D;
    float* h2   = out0 + 2 * (size_t)N * D;

    int nd4 = N * (D / 4);
    int nb = (N + SCAN_BLK - 1) / SCAN_BLK;

    cudaFuncSetAttribute(sage_gemm_kernel,
                         cudaFuncAttributeMaxDynamicSharedMemorySize, SMEM_BYTES);

    copy_convert_kernel<<<(nd4 + 255) / 256, 256>>>(feat, out0, nd4, N);
    hist_kernel<<<(E + 255) / 256, 256>>>(dst, E);
    scan_blocks_kernel<<<nb, SCAN_BLK>>>(N);
    scan_add_kernel<<<(N + 255) / 256, 256>>>(N, E);
    fill_kernel<<<(E + 255) / 256, 256>>>(src, dst, E);

    gather_kernel<<<(N + 7) / 8, 256>>>(feat, N);

    wconv_kernel<<<dim3((256 * 256 + 255) / 256, 2), 256>>>(Ws0, Wn0, Ws1, Wn1);

    dim3 ggrid(2, (N + 127) / 128);

    sage_gemm_kernel<<<ggrid, 256, SMEM_BYTES>>>(b0, a1, N, 0, 1);
    gather_kernel<<<(N + 7) / 8, 256>>>(a1, N);
    sage_gemm_kernel<<<ggrid, 256, SMEM_BYTES>>>(b1, h2, N, 1, 0);
}

// round 12
// speedup vs baseline: 1.2604x; 1.1830x over previous
#include <cuda_runtime.h>
#include <cuda_fp16.h>
#include <cstddef>
#include <cstdint>

#define D 256
#define N_MAX 100000
#define E_MAX 1600000
#define SCAN_BLK 1024

// R8: harness PTX targets compute_103 (no 'a') -> tcgen05 unavailable; legacy mma only.
// R10: all kernels saturate the chip -> stream overlap is additive; single stream.
// R11: GEMM at legacy-HMMA issue floor -> cut MMA count algorithmically (fp16 2-product).

// ---- scratch (__device__ globals; allocation-free rule) ----
__device__ uint32_t g_feat_hi[(size_t)N_MAX * 128];  // fp16x2 words, [row][128]
__device__ uint32_t g_feat_lo[(size_t)N_MAX * 128];
__device__ uint32_t g_a1_hi[(size_t)N_MAX * 128];
__device__ uint32_t g_a1_lo[(size_t)N_MAX * 128];
__device__ uint32_t g_nhi[(size_t)N_MAX * 128];
__device__ uint32_t g_nlo[(size_t)N_MAX * 128];
__device__ uint32_t g_wth[2][256 * 256];             // W^T hi: [n][512k as 256 words]
__device__ int g_cnt[N_MAX];
__device__ int g_off[N_MAX + 1];
__device__ int g_cursor[N_MAX];
__device__ int g_bsum[(N_MAX + SCAN_BLK - 1) / SCAN_BLK + 1];
__device__ int g_esrc[E_MAX];

// ---- fp16 split helpers ----
__device__ __forceinline__ void split1(float x, float& h, float& l) {
    h = __half2float(__float2half_rn(x));
    l = x - h;
}
__device__ __forceinline__ uint32_t pack2(float lo_elem, float hi_elem) {
    __half2 t = __floats2half2_rn(lo_elem, hi_elem);  // .x = low half
    return *reinterpret_cast<uint32_t*>(&t);
}
__device__ __forceinline__ void split4(float4 v, uint32_t* hw, uint32_t* lw) {
    float h0, l0, h1, l1, h2, l2, h3, l3;
    split1(v.x, h0, l0); split1(v.y, h1, l1);
    split1(v.z, h2, l2); split1(v.w, h3, l3);
    hw[0] = pack2(h0, h1); hw[1] = pack2(h2, h3);
    lw[0] = pack2(l0, l1); lw[1] = pack2(l2, l3);
}

// ---------------------------------------------------------------------------
// copy feat -> out[0], split to g_feat_hi/lo, AND zero g_cnt (fused)
__global__ void copy_convert_kernel(const float* __restrict__ in,
                                    float* __restrict__ out, int n4, int N) {
    int i = blockIdx.x * blockDim.x + threadIdx.x;
    if (i < N) g_cnt[i] = 0;
    if (i >= n4) return;
    float4 v = ((const float4*)in)[i];
    ((float4*)out)[i] = v;
    uint32_t hw[2], lw[2];
    split4(v, hw, lw);
    *(uint2*)&g_feat_hi[(size_t)i * 2] = make_uint2(hw[0], hw[1]);
    *(uint2*)&g_feat_lo[(size_t)i * 2] = make_uint2(lw[0], lw[1]);
}

__global__ void hist_kernel(const int* __restrict__ dst, int E) {
    int i = blockIdx.x * blockDim.x + threadIdx.x;
    if (i < E) atomicAdd(&g_cnt[dst[i]], 1);
}

__global__ void scan_blocks_kernel(int n) {
    __shared__ int sm[SCAN_BLK];
    int tid = threadIdx.x;
    int i = blockIdx.x * SCAN_BLK + tid;
    int v = (i < n) ? g_cnt[i] : 0;
    sm[tid] = v;
    __syncthreads();
#pragma unroll
    for (int off = 1; off < SCAN_BLK; off <<= 1) {
        int t = (tid >= off) ? sm[tid - off] : 0;
        __syncthreads();
        sm[tid] += t;
        __syncthreads();
    }
    if (i < n) g_off[i] = sm[tid] - v;
    if (tid == SCAN_BLK - 1) g_bsum[blockIdx.x] = sm[tid];
}

__global__ void scan_add_kernel(int n, int E) {
    __shared__ int pref;
    int g = (blockIdx.x * 256) >> 10;
    if (threadIdx.x < 32) {
        int s = 0;
        for (int j = threadIdx.x; j < g; j += 32) s += g_bsum[j];
#pragma unroll
        for (int o = 16; o; o >>= 1) s += __shfl_down_sync(0xFFFFFFFFu, s, o);
        if (threadIdx.x == 0) pref = s;
    }
    __syncthreads();
    int i = blockIdx.x * 256 + threadIdx.x;
    if (i < n) {
        int v = g_off[i] + pref;
        g_off[i] = v;
        g_cursor[i] = v;
    }
    if (i == 0) g_off[n] = E;
}

__global__ void fill_kernel(const int* __restrict__ src,
                            const int* __restrict__ dst, int E) {
    int e = blockIdx.x * blockDim.x + threadIdx.x;
    if (e < E) {
        int d = dst[e];
        int p = atomicAdd(&g_cursor[d], 1);
        g_esrc[p] = src[e];
    }
}

// transpose + fp16 weights (hi only), both layers in one launch
__global__ void wconv_kernel(const float* __restrict__ Ws0, const float* __restrict__ Wn0,
                             const float* __restrict__ Ws1, const float* __restrict__ Wn1) {
    int idx = blockIdx.x * blockDim.x + threadIdx.x;
    if (idx >= 256 * 256) return;
    int layer = blockIdx.y;
    const float* Ws = layer ? Ws1 : Ws0;
    const float* Wn = layer ? Wn1 : Wn0;
    int n = idx & 255;
    int wp = idx >> 8;
    int k0 = wp * 2, k1 = k0 + 1;
    float v0 = (k0 < 256) ? Ws[k0 * 256 + n] : Wn[(k0 - 256) * 256 + n];
    float v1 = (k1 < 256) ? Ws[k1 * 256 + n] : Wn[(k1 - 256) * 256 + n];
    __half2 t = __floats2half2_rn(v0, v1);
    g_wth[layer][n * 256 + wp] = *reinterpret_cast<uint32_t*>(&t);
}

// ---------------------------------------------------------------------------
// Gather aggregation: one warp per dst node; 4-edge unroll; fp16 hi/lo output.
__global__ void gather_kernel(const float* __restrict__ X, int N) {
    int node = blockIdx.x * 8 + (threadIdx.x >> 5);
    if (node >= N) return;
    int lane = threadIdx.x & 31;

    int beg = g_off[node];
    int end = g_off[node + 1];

    float4 a0 = make_float4(0.f, 0.f, 0.f, 0.f);
    float4 a1 = make_float4(0.f, 0.f, 0.f, 0.f);

    int i = beg;
    for (; i + 3 < end; i += 4) {
        int s0 = __ldg(g_esrc + i);
        int s1 = __ldg(g_esrc + i + 1);
        int s2 = __ldg(g_esrc + i + 2);
        int s3 = __ldg(g_esrc + i + 3);
        const float4* x0 = (const float4*)(X + (size_t)s0 * D);
        const float4* x1 = (const float4*)(X + (size_t)s1 * D);
        const float4* x2 = (const float4*)(X + (size_t)s2 * D);
        const float4* x3 = (const float4*)(X + (size_t)s3 * D);
        float4 v00 = __ldg(x0 + lane), v01 = __ldg(x0 + lane + 32);
        float4 v10 = __ldg(x1 + lane), v11 = __ldg(x1 + lane + 32);
        float4 v20 = __ldg(x2 + lane), v21 = __ldg(x2 + lane + 32);
        float4 v30 = __ldg(x3 + lane), v31 = __ldg(x3 + lane + 32);
        a0.x += (v00.x + v10.x) + (v20.x + v30.x);
        a0.y += (v00.y + v10.y) + (v20.y + v30.y);
        a0.z += (v00.z + v10.z) + (v20.z + v30.z);
        a0.w += (v00.w + v10.w) + (v20.w + v30.w);
        a1.x += (v01.x + v11.x) + (v21.x + v31.x);
        a1.y += (v01.y + v11.y) + (v21.y + v31.y);
        a1.z += (v01.z + v11.z) + (v21.z + v31.z);
        a1.w += (v01.w + v11.w) + (v21.w + v31.w);
    }
    for (; i < end; ++i) {
        int s0 = __ldg(g_esrc + i);
        const float4* x0 = (const float4*)(X + (size_t)s0 * D);
        float4 v00 = __ldg(x0 + lane);
        float4 v01 = __ldg(x0 + lane + 32);
        a0.x += v00.x; a0.y += v00.y; a0.z += v00.z; a0.w += v00.w;
        a1.x += v01.x; a1.y += v01.y; a1.z += v01.z; a1.w += v01.w;
    }

    float inv = (end > beg) ? (1.0f / (float)(end - beg)) : 0.f;
    a0.x *= inv; a0.y *= inv; a0.z *= inv; a0.w *= inv;
    a1.x *= inv; a1.y *= inv; a1.z *= inv; a1.w *= inv;

    uint32_t hw[2], lw[2];
    size_t base = (size_t)node * 128;
    split4(a0, hw, lw);
    *(uint2*)&g_nhi[base + lane * 2] = make_uint2(hw[0], hw[1]);
    *(uint2*)&g_nlo[base + lane * 2] = make_uint2(lw[0], lw[1]);
    split4(a1, hw, lw);
    *(uint2*)&g_nhi[base + 64 + lane * 2] = make_uint2(hw[0], hw[1]);
    *(uint2*)&g_nlo[base + 64 + lane * 2] = make_uint2(lw[0], lw[1]);
}

// ---------------------------------------------------------------------------
// fp16 2-product tensor GEMM: out = (Ah + Al) @ Bh^T, fp32 accum.
// CTA 128x128, warp 32x64, K=512 fused. Per warp-iter: 16 LDSM + 64 MMA.
#define T_STR 20
#define SA_SZ (128 * T_STR)
#define SB_SZ (128 * T_STR)
#define SMEM_WORDS (2 * (2 * SA_SZ + SB_SZ))
#define SMEM_BYTES (SMEM_WORDS * 4)

__device__ __forceinline__ void cp_async16(void* s, const void* g, bool pred) {
    uint32_t sa = (uint32_t)__cvta_generic_to_shared(s);
    int sz = pred ? 16 : 0;
    asm volatile("cp.async.cg.shared.global [%0], [%1], 16, %2;"
                 :: "r"(sa), "l"(g), "r"(sz) : "memory");
}

__device__ __forceinline__ void mma_f16(float* c, const uint32_t* a, const uint32_t* b) {
    asm volatile(
        "mma.sync.aligned.m16n8k16.row.col.f32.f16.f16.f32 "
        "{%0,%1,%2,%3}, {%4,%5,%6,%7}, {%8,%9}, {%0,%1,%2,%3};"
        : "+f"(c[0]), "+f"(c[1]), "+f"(c[2]), "+f"(c[3])
        : "r"(a[0]), "r"(a[1]), "r"(a[2]), "r"(a[3]), "r"(b[0]), "r"(b[1]));
}

__device__ __forceinline__ void ldsm_x4(uint32_t* r, uint32_t addr) {
    asm volatile("ldmatrix.sync.aligned.m8n8.x4.shared.b16 {%0,%1,%2,%3}, [%4];"
                 : "=r"(r[0]), "=r"(r[1]), "=r"(r[2]), "=r"(r[3]) : "r"(addr));
}

__global__ void __launch_bounds__(256, 2) sage_gemm_kernel(
    const float* __restrict__ bias,
    float* __restrict__ out,
    int M, int layer, int do_relu) {
    extern __shared__ uint32_t smem[];
    uint32_t* sAh = smem;                       // 2 stages x [128][T_STR]
    uint32_t* sAl = smem + 2 * SA_SZ;
    uint32_t* sBh = smem + 4 * SA_SZ;           // 2 stages x [128][T_STR]
    const uint32_t smem_u32 = (uint32_t)__cvta_generic_to_shared(smem);

    const int tid = threadIdx.x;
    const int lane = tid & 31;
    const int wid = tid >> 5;
    const int wm = wid >> 1;          // 0..3  (m32 each)
    const int wn = wid & 1;           // 0..1  (n64 each)
    const int bm = blockIdx.y * 128;
    const int bn = blockIdx.x * 128;

    const uint32_t* Xhi = layer ? g_a1_hi : g_feat_hi;
    const uint32_t* Xlo = layer ? g_a1_lo : g_feat_lo;
    const uint32_t* Wh = g_wth[layer];

    float acc[2][8][4] = {};

    auto load_tile = [&](int it, int buf) {
        int kg = it * 32;
        const uint32_t* Ah = (kg < 256) ? Xhi : (const uint32_t*)g_nhi;
        const uint32_t* Al = (kg < 256) ? Xlo : (const uint32_t*)g_nlo;
        int klw = (kg & 255) >> 1;
        uint32_t* dAh = sAh + buf * SA_SZ;
        uint32_t* dAl = sAl + buf * SA_SZ;
        uint32_t* dBh = sBh + buf * SB_SZ;
#pragma unroll
        for (int i = 0; i < 2; ++i) {            // A: 128 rows x 4 chunks
            int ci = i * 256 + tid;
            int row = ci >> 2, ch = ci & 3;
            int grow = bm + row;
            bool ok = grow < M;
            size_t off = (size_t)(ok ? grow : (M - 1)) * 128 + klw + ch * 4;
            cp_async16(dAh + row * T_STR + ch * 4, Ah + off, ok);
            cp_async16(dAl + row * T_STR + ch * 4, Al + off, ok);
        }
#pragma unroll
        for (int i = 0; i < 2; ++i) {            // B: 128 rows x 4 chunks (hi only)
            int ci = i * 256 + tid;
            int row = ci >> 2, ch = ci & 3;
            size_t off = (size_t)(bn + row) * 256 + it * 16 + ch * 4;
            cp_async16(dBh + row * T_STR + ch * 4, Wh + off, true);
        }
    };

    load_tile(0, 0);
    asm volatile("cp.async.commit_group;" ::: "memory");

    const int a_r = wm * 32 + (lane & 15);
    const int a_w = (lane >> 4) << 2;
    const int b_r = wn * 64 + (lane & 7) + ((lane >> 4) << 3);
    const int b_w = ((lane >> 3) & 1) << 2;

    const int K_ITERS = 512 / 32;  // 16
#pragma unroll 1
    for (int it = 0; it < K_ITERS; ++it) {
        if (it + 1 < K_ITERS) {
            load_tile(it + 1, (it + 1) & 1);
            asm volatile("cp.async.commit_group;" ::: "memory");
            asm volatile("cp.async.wait_group 1;" ::: "memory");
        } else {
            asm volatile("cp.async.wait_group 0;" ::: "memory");
        }
        __syncthreads();

        const uint32_t aHb = smem_u32 + ((it & 1) * SA_SZ) * 4;
        const uint32_t aLb = aHb + (2 * SA_SZ) * 4;
        const uint32_t bHb = smem_u32 + (4 * SA_SZ + (it & 1) * SB_SZ) * 4;

#pragma unroll
        for (int ks = 0; ks < 2; ++ks) {
            uint32_t ah[2][4], al[2][4];
#pragma unroll
            for (int mt = 0; mt < 2; ++mt) {
                uint32_t off = (uint32_t)(((a_r + mt * 16) * T_STR + a_w + ks * 8) * 4);
                ldsm_x4(ah[mt], aHb + off);
                ldsm_x4(al[mt], aLb + off);
            }
#pragma unroll
            for (int np = 0; np < 4; ++np) {
                uint32_t off = (uint32_t)(((b_r + np * 16) * T_STR + b_w + ks * 8) * 4);
                uint32_t th[4];
                ldsm_x4(th, bHb + off);
#pragma unroll
                for (int mt = 0; mt < 2; ++mt) {
#pragma unroll
                    for (int sub = 0; sub < 2; ++sub) {
                        float* a = acc[mt][np * 2 + sub];
                        mma_f16(a, al[mt], th + sub * 2);  // small term first
                        mma_f16(a, ah[mt], th + sub * 2);
                    }
                }
            }
        }
        __syncthreads();
    }

    // ---- epilogue: bias (+relu); layer 0 also writes a1 hi/lo fp16 ----
#pragma unroll
    for (int mt = 0; mt < 2; ++mt) {
        int r0 = bm + wm * 32 + mt * 16 + (lane >> 2);
#pragma unroll
        for (int nt = 0; nt < 8; ++nt) {
            int cc = bn + wn * 64 + nt * 8 + (lane & 3) * 2;
            float bx = __ldg(bias + cc);
            float by = __ldg(bias + cc + 1);
            float2 v0, v1;
            v0.x = acc[mt][nt][0] + bx; v0.y = acc[mt][nt][1] + by;
            v1.x = acc[mt][nt][2] + bx; v1.y = acc[mt][nt][3] + by;
            if (do_relu) {
                v0.x = fmaxf(v0.x, 0.f); v0.y = fmaxf(v0.y, 0.f);
                v1.x = fmaxf(v1.x, 0.f); v1.y = fmaxf(v1.y, 0.f);
            }
            if (r0 < M) {
                *(float2*)(out + (size_t)r0 * 256 + cc) = v0;
                if (do_relu) {
                    float h0, l0, h1, l1;
                    split1(v0.x, h0, l0); split1(v0.y, h1, l1);
                    g_a1_hi[(size_t)r0 * 128 + (cc >> 1)] = pack2(h0, h1);
                    g_a1_lo[(size_t)r0 * 128 + (cc >> 1)] = pack2(l0, l1);
                }
            }
            if (r0 + 8 < M) {
                *(float2*)(out + (size_t)(r0 + 8) * 256 + cc) = v1;
                if (do_relu) {
                    float h0, l0, h1, l1;
                    split1(v1.x, h0, l0); split1(v1.y, h1, l1);
                    g_a1_hi[(size_t)(r0 + 8) * 128 + (cc >> 1)] = pack2(h0, h1);
                    g_a1_lo[(size_t)(r0 + 8) * 128 + (cc >> 1)] = pack2(l0, l1);
                }
            }
        }
    }
}

// ---------------------------------------------------------------------------
extern "C" void kernel_launch(void* const* d_in, const int* in_sizes, int n_in,
                              void* d_out, int out_size) {
    const float* feat = (const float*)d_in[0];
    const int*   src  = (const int*)d_in[1];
    const int*   dst  = (const int*)d_in[2];
    const float* Ws0  = (const float*)d_in[3];
    const float* Wn0  = (const float*)d_in[4];
    const float* b0   = (const float*)d_in[5];
    const float* Ws1  = (const float*)d_in[6];
    const float* Wn1  = (const float*)d_in[7];
    const float* b1   = (const float*)d_in[8];

    int N = in_sizes[0] / D;   // 100000
    int E = in_sizes[1];       // 1600000

    float* out0 = (float*)d_out;
    float* a1   = out0 + (size_t)N * D;
    float* h2   = out0 + 2 * (size_t)N * D;

    int nd4 = N * (D / 4);
    int nb = (N + SCAN_BLK - 1) / SCAN_BLK;

    cudaFuncSetAttribute(sage_gemm_kernel,
                         cudaFuncAttributeMaxDynamicSharedMemorySize, SMEM_BYTES);

    copy_convert_kernel<<<(nd4 + 255) / 256, 256>>>(feat, out0, nd4, N);
    hist_kernel<<<(E + 255) / 256, 256>>>(dst, E);
    scan_blocks_kernel<<<nb, SCAN_BLK>>>(N);
    scan_add_kernel<<<(N + 255) / 256, 256>>>(N, E);
    fill_kernel<<<(E + 255) / 256, 256>>>(src, dst, E);

    gather_kernel<<<(N + 7) / 8, 256>>>(feat, N);

    wconv_kernel<<<dim3((256 * 256 + 255) / 256, 2), 256>>>(Ws0, Wn0, Ws1, Wn1);

    dim3 ggrid(2, (N + 127) / 128);

    sage_gemm_kernel<<<ggrid, 256, SMEM_BYTES>>>(b0, a1, N, 0, 1);
    gather_kernel<<<(N + 7) / 8, 256>>>(a1, N);
    sage_gemm_kernel<<<ggrid, 256, SMEM_BYTES>>>(b1, h2, N, 1, 0);
}

// round 13
// speedup vs baseline: 1.7218x; 1.3661x over previous
#include <cuda_runtime.h>
#include <cuda_fp16.h>
#include <cstddef>
#include <cstdint>

#define D 256
#define N_MAX 100000
#define E_MAX 1600000
#define SCAN_BLK 1024

// R2:  NEVER pass __device__ symbols as host-side kernel args (ATS shadow -> zeros).
// R8:  harness PTX targets compute_103 (no 'a') -> tcgen05 unavailable; legacy mma only.
// R10: all kernels saturate the chip -> single stream; per-kernel efficiency only.
// R11: GEMM at legacy-HMMA issue floor -> cut MMA count algorithmically.
// R12: fp16 2-product validated (2.36e-4, 4x margin).

// ---- scratch (__device__ globals; allocation-free rule) ----
__device__ uint32_t g_feat_hi[(size_t)N_MAX * 128];  // fp16x2 words, [row][128]
__device__ uint32_t g_feat_lo[(size_t)N_MAX * 128];
__device__ uint32_t g_a1_hi[(size_t)N_MAX * 128];
__device__ uint32_t g_a1_lo[(size_t)N_MAX * 128];
__device__ uint32_t g_nhi[(size_t)N_MAX * 128];      // neigh aggregate, fp16 hi only
__device__ uint32_t g_wth[2][256 * 256];             // W^T hi: [n][512k as 256 words]
__device__ int g_cnt[N_MAX];
__device__ int g_off[N_MAX + 1];
__device__ int g_cursor[N_MAX];
__device__ int g_bsum[(N_MAX + SCAN_BLK - 1) / SCAN_BLK + 1];
__device__ int g_esrc[E_MAX];

// ---- fp16 split helpers ----
__device__ __forceinline__ void split1(float x, float& h, float& l) {
    h = __half2float(__float2half_rn(x));
    l = x - h;
}
__device__ __forceinline__ uint32_t pack2(float lo_elem, float hi_elem) {
    __half2 t = __floats2half2_rn(lo_elem, hi_elem);  // .x = low half
    return *reinterpret_cast<uint32_t*>(&t);
}
__device__ __forceinline__ void split4(float4 v, uint32_t* hw, uint32_t* lw) {
    float h0, l0, h1, l1, h2, l2, h3, l3;
    split1(v.x, h0, l0); split1(v.y, h1, l1);
    split1(v.z, h2, l2); split1(v.w, h3, l3);
    hw[0] = pack2(h0, h1); hw[1] = pack2(h2, h3);
    lw[0] = pack2(l0, l1); lw[1] = pack2(l2, l3);
}
__device__ __forceinline__ void acc_word(float* a, uint32_t w) {
    float2 f = __half22float2(*reinterpret_cast<__half2*>(&w));
    a[0] += f.x; a[1] += f.y;
}

// ---------------------------------------------------------------------------
// copy feat -> out[0], split to g_feat_hi/lo, AND zero g_cnt (fused)
__global__ void copy_convert_kernel(const float* __restrict__ in,
                                    float* __restrict__ out, int n4, int N) {
    int i = blockIdx.x * blockDim.x + threadIdx.x;
    if (i < N) g_cnt[i] = 0;
    if (i >= n4) return;
    float4 v = ((const float4*)in)[i];
    ((float4*)out)[i] = v;
    uint32_t hw[2], lw[2];
    split4(v, hw, lw);
    *(uint2*)&g_feat_hi[(size_t)i * 2] = make_uint2(hw[0], hw[1]);
    *(uint2*)&g_feat_lo[(size_t)i * 2] = make_uint2(lw[0], lw[1]);
}

__global__ void hist_kernel(const int* __restrict__ dst, int E) {
    int i = blockIdx.x * blockDim.x + threadIdx.x;
    if (i < E) atomicAdd(&g_cnt[dst[i]], 1);
}

__global__ void scan_blocks_kernel(int n) {
    __shared__ int sm[SCAN_BLK];
    int tid = threadIdx.x;
    int i = blockIdx.x * SCAN_BLK + tid;
    int v = (i < n) ? g_cnt[i] : 0;
    sm[tid] = v;
    __syncthreads();
#pragma unroll
    for (int off = 1; off < SCAN_BLK; off <<= 1) {
        int t = (tid >= off) ? sm[tid - off] : 0;
        __syncthreads();
        sm[tid] += t;
        __syncthreads();
    }
    if (i < n) g_off[i] = sm[tid] - v;
    if (tid == SCAN_BLK - 1) g_bsum[blockIdx.x] = sm[tid];
}

__global__ void scan_add_kernel(int n, int E) {
    __shared__ int pref;
    int g = (blockIdx.x * 256) >> 10;
    if (threadIdx.x < 32) {
        int s = 0;
        for (int j = threadIdx.x; j < g; j += 32) s += g_bsum[j];
#pragma unroll
        for (int o = 16; o; o >>= 1) s += __shfl_down_sync(0xFFFFFFFFu, s, o);
        if (threadIdx.x == 0) pref = s;
    }
    __syncthreads();
    int i = blockIdx.x * 256 + threadIdx.x;
    if (i < n) {
        int v = g_off[i] + pref;
        g_off[i] = v;
        g_cursor[i] = v;
    }
    if (i == 0) g_off[n] = E;
}

__global__ void fill_kernel(const int* __restrict__ src,
                            const int* __restrict__ dst, int E) {
    int e = blockIdx.x * blockDim.x + threadIdx.x;
    if (e < E) {
        int d = dst[e];
        int p = atomicAdd(&g_cursor[d], 1);
        g_esrc[p] = src[e];
    }
}

// transpose + fp16 weights (hi only), both layers in one launch
__global__ void wconv_kernel(const float* __restrict__ Ws0, const float* __restrict__ Wn0,
                             const float* __restrict__ Ws1, const float* __restrict__ Wn1) {
    int idx = blockIdx.x * blockDim.x + threadIdx.x;
    if (idx >= 256 * 256) return;
    int layer = blockIdx.y;
    const float* Ws = layer ? Ws1 : Ws0;
    const float* Wn = layer ? Wn1 : Wn0;
    int n = idx & 255;
    int wp = idx >> 8;
    int k0 = wp * 2, k1 = k0 + 1;
    float v0 = (k0 < 256) ? Ws[k0 * 256 + n] : Wn[(k0 - 256) * 256 + n];
    float v1 = (k1 < 256) ? Ws[k1 * 256 + n] : Wn[(k1 - 256) * 256 + n];
    __half2 t = __floats2half2_rn(v0, v1);
    g_wth[layer][n * 256 + wp] = *reinterpret_cast<uint32_t*>(&t);
}

// ---------------------------------------------------------------------------
// Gather aggregation from fp16-hi rows (512B/edge): one warp per dst node,
// lane covers 8 elems (one uint4). fp32 accumulate, fp16-hi output only.
// layer selects the DEVICE-side source symbol (R2 lesson).
__global__ void gather_kernel(int layer, int N) {
    int node = blockIdx.x * 8 + (threadIdx.x >> 5);
    if (node >= N) return;
    int lane = threadIdx.x & 31;

    const uint32_t* Xh = layer ? g_a1_hi : g_feat_hi;

    int beg = g_off[node];
    int end = g_off[node + 1];

    float a[8] = {};

    int i = beg;
    for (; i + 3 < end; i += 4) {
        int s0 = __ldg(g_esrc + i);
        int s1 = __ldg(g_esrc + i + 1);
        int s2 = __ldg(g_esrc + i + 2);
        int s3 = __ldg(g_esrc + i + 3);
        uint4 w0 = __ldg((const uint4*)(Xh + (size_t)s0 * 128) + lane);
        uint4 w1 = __ldg((const uint4*)(Xh + (size_t)s1 * 128) + lane);
        uint4 w2 = __ldg((const uint4*)(Xh + (size_t)s2 * 128) + lane);
        uint4 w3 = __ldg((const uint4*)(Xh + (size_t)s3 * 128) + lane);
        acc_word(a + 0, w0.x); acc_word(a + 2, w0.y);
        acc_word(a + 4, w0.z); acc_word(a + 6, w0.w);
        acc_word(a + 0, w1.x); acc_word(a + 2, w1.y);
        acc_word(a + 4, w1.z); acc_word(a + 6, w1.w);
        acc_word(a + 0, w2.x); acc_word(a + 2, w2.y);
        acc_word(a + 4, w2.z); acc_word(a + 6, w2.w);
        acc_word(a + 0, w3.x); acc_word(a + 2, w3.y);
        acc_word(a + 4, w3.z); acc_word(a + 6, w3.w);
    }
    for (; i < end; ++i) {
        int s0 = __ldg(g_esrc + i);
        uint4 w0 = __ldg((const uint4*)(Xh + (size_t)s0 * 128) + lane);
        acc_word(a + 0, w0.x); acc_word(a + 2, w0.y);
        acc_word(a + 4, w0.z); acc_word(a + 6, w0.w);
    }

    float inv = (end > beg) ? (1.0f / (float)(end - beg)) : 0.f;
    uint4 ow;
    ow.x = pack2(a[0] * inv, a[1] * inv);
    ow.y = pack2(a[2] * inv, a[3] * inv);
    ow.z = pack2(a[4] * inv, a[5] * inv);
    ow.w = pack2(a[6] * inv, a[7] * inv);
    *((uint4*)(g_nhi + (size_t)node * 128) + lane) = ow;
}

// ---------------------------------------------------------------------------
// fp16 tensor GEMM: self half (K 0..255) = 2 products (Ah+Al)Bh;
// neigh half (K 256..511) = 1 product (hi-only aggregate). fp32 accum.
// CTA 128x128, warp 32x64.
#define T_STR 20
#define SA_SZ (128 * T_STR)
#define SB_SZ (128 * T_STR)
#define SMEM_WORDS (2 * (2 * SA_SZ + SB_SZ))
#define SMEM_BYTES (SMEM_WORDS * 4)

__device__ __forceinline__ void cp_async16(void* s, const void* g, bool pred) {
    uint32_t sa = (uint32_t)__cvta_generic_to_shared(s);
    int sz = pred ? 16 : 0;
    asm volatile("cp.async.cg.shared.global [%0], [%1], 16, %2;"
                 :: "r"(sa), "l"(g), "r"(sz) : "memory");
}

__device__ __forceinline__ void mma_f16(float* c, const uint32_t* a, const uint32_t* b) {
    asm volatile(
        "mma.sync.aligned.m16n8k16.row.col.f32.f16.f16.f32 "
        "{%0,%1,%2,%3}, {%4,%5,%6,%7}, {%8,%9}, {%0,%1,%2,%3};"
        : "+f"(c[0]), "+f"(c[1]), "+f"(c[2]), "+f"(c[3])
        : "r"(a[0]), "r"(a[1]), "r"(a[2]), "r"(a[3]), "r"(b[0]), "r"(b[1]));
}

__device__ __forceinline__ void ldsm_x4(uint32_t* r, uint32_t addr) {
    asm volatile("ldmatrix.sync.aligned.m8n8.x4.shared.b16 {%0,%1,%2,%3}, [%4];"
                 : "=r"(r[0]), "=r"(r[1]), "=r"(r[2]), "=r"(r[3]) : "r"(addr));
}

__global__ void __launch_bounds__(256, 2) sage_gemm_kernel(
    const float* __restrict__ bias,
    float* __restrict__ out,
    int M, int layer, int do_relu) {
    extern __shared__ uint32_t smem[];
    uint32_t* sAh = smem;                       // 2 stages x [128][T_STR]
    uint32_t* sAl = smem + 2 * SA_SZ;           // used only for it < 8
    uint32_t* sBh = smem + 4 * SA_SZ;
    const uint32_t smem_u32 = (uint32_t)__cvta_generic_to_shared(smem);

    const int tid = threadIdx.x;
    const int lane = tid & 31;
    const int wid = tid >> 5;
    const int wm = wid >> 1;          // 0..3  (m32 each)
    const int wn = wid & 1;           // 0..1  (n64 each)
    const int bm = blockIdx.y * 128;
    const int bn = blockIdx.x * 128;

    const uint32_t* Xhi = layer ? g_a1_hi : g_feat_hi;
    const uint32_t* Xlo = layer ? g_a1_lo : g_feat_lo;
    const uint32_t* Wh = g_wth[layer];

    float acc[2][8][4] = {};

    auto load_tile = [&](int it, int buf) {
        bool self_ph = (it < 8);
        const uint32_t* Ah = self_ph ? Xhi : (const uint32_t*)g_nhi;
        int klw = (it & 7) * 16;
        uint32_t* dAh = sAh + buf * SA_SZ;
        uint32_t* dAl = sAl + buf * SA_SZ;
        uint32_t* dBh = sBh + buf * SB_SZ;
#pragma unroll
        for (int i = 0; i < 2; ++i) {            // A hi (+lo in self phase)
            int ci = i * 256 + tid;
            int row = ci >> 2, ch = ci & 3;
            int grow = bm + row;
            bool ok = grow < M;
            size_t off = (size_t)(ok ? grow : (M - 1)) * 128 + klw + ch * 4;
            cp_async16(dAh + row * T_STR + ch * 4, Ah + off, ok);
            if (self_ph)
                cp_async16(dAl + row * T_STR + ch * 4, Xlo + off, ok);
        }
#pragma unroll
        for (int i = 0; i < 2; ++i) {            // B hi: 128 rows x 4 chunks
            int ci = i * 256 + tid;
            int row = ci >> 2, ch = ci & 3;
            size_t off = (size_t)(bn + row) * 256 + it * 16 + ch * 4;
            cp_async16(dBh + row * T_STR + ch * 4, Wh + off, true);
        }
    };

    load_tile(0, 0);
    asm volatile("cp.async.commit_group;" ::: "memory");

    const int a_r = wm * 32 + (lane & 15);
    const int a_w = (lane >> 4) << 2;
    const int b_r = wn * 64 + (lane & 7) + ((lane >> 4) << 3);
    const int b_w = ((lane >> 3) & 1) << 2;

    const int K_ITERS = 512 / 32;  // 16
#pragma unroll 1
    for (int it = 0; it < K_ITERS; ++it) {
        if (it + 1 < K_ITERS) {
            load_tile(it + 1, (it + 1) & 1);
            asm volatile("cp.async.commit_group;" ::: "memory");
            asm volatile("cp.async.wait_group 1;" ::: "memory");
        } else {
            asm volatile("cp.async.wait_group 0;" ::: "memory");
        }
        __syncthreads();

        const bool self_ph = (it < 8);
        const uint32_t aHb = smem_u32 + ((it & 1) * SA_SZ) * 4;
        const uint32_t aLb = aHb + (2 * SA_SZ) * 4;
        const uint32_t bHb = smem_u32 + (4 * SA_SZ + (it & 1) * SB_SZ) * 4;

#pragma unroll
        for (int ks = 0; ks < 2; ++ks) {
            uint32_t ah[2][4], al[2][4];
#pragma unroll
            for (int mt = 0; mt < 2; ++mt) {
                uint32_t off = (uint32_t)(((a_r + mt * 16) * T_STR + a_w + ks * 8) * 4);
                ldsm_x4(ah[mt], aHb + off);
                if (self_ph) ldsm_x4(al[mt], aLb + off);
            }
#pragma unroll
            for (int np = 0; np < 4; ++np) {
                uint32_t off = (uint32_t)(((b_r + np * 16) * T_STR + b_w + ks * 8) * 4);
                uint32_t th[4];
                ldsm_x4(th, bHb + off);
#pragma unroll
                for (int mt = 0; mt < 2; ++mt) {
#pragma unroll
                    for (int sub = 0; sub < 2; ++sub) {
                        float* a = acc[mt][np * 2 + sub];
                        if (self_ph) mma_f16(a, al[mt], th + sub * 2);
                        mma_f16(a, ah[mt], th + sub * 2);
                    }
                }
            }
        }
        __syncthreads();
    }

    // ---- epilogue: bias (+relu); layer 0 also writes a1 hi/lo fp16 ----
#pragma unroll
    for (int mt = 0; mt < 2; ++mt) {
        int r0 = bm + wm * 32 + mt * 16 + (lane >> 2);
#pragma unroll
        for (int nt = 0; nt < 8; ++nt) {
            int cc = bn + wn * 64 + nt * 8 + (lane & 3) * 2;
            float bx = __ldg(bias + cc);
            float by = __ldg(bias + cc + 1);
            float2 v0, v1;
            v0.x = acc[mt][nt][0] + bx; v0.y = acc[mt][nt][1] + by;
            v1.x = acc[mt][nt][2] + bx; v1.y = acc[mt][nt][3] + by;
            if (do_relu) {
                v0.x = fmaxf(v0.x, 0.f); v0.y = fmaxf(v0.y, 0.f);
                v1.x = fmaxf(v1.x, 0.f); v1.y = fmaxf(v1.y, 0.f);
            }
            if (r0 < M) {
                *(float2*)(out + (size_t)r0 * 256 + cc) = v0;
                if (do_relu) {
                    float h0, l0, h1, l1;
                    split1(v0.x, h0, l0); split1(v0.y, h1, l1);
                    g_a1_hi[(size_t)r0 * 128 + (cc >> 1)] = pack2(h0, h1);
                    g_a1_lo[(size_t)r0 * 128 + (cc >> 1)] = pack2(l0, l1);
                }
            }
            if (r0 + 8 < M) {
                *(float2*)(out + (size_t)(r0 + 8) * 256 + cc) = v1;
                if (do_relu) {
                    float h0, l0, h1, l1;
                    split1(v1.x, h0, l0); split1(v1.y, h1, l1);
                    g_a1_hi[(size_t)(r0 + 8) * 128 + (cc >> 1)] = pack2(h0, h1);
                    g_a1_lo[(size_t)(r0 + 8) * 128 + (cc >> 1)] = pack2(l0, l1);
                }
            }
        }
    }
}

// ---------------------------------------------------------------------------
extern "C" void kernel_launch(void* const* d_in, const int* in_sizes, int n_in,
                              void* d_out, int out_size) {
    const float* feat = (const float*)d_in[0];
    const int*   src  = (const int*)d_in[1];
    const int*   dst  = (const int*)d_in[2];
    const float* Ws0  = (const float*)d_in[3];
    const float* Wn0  = (const float*)d_in[4];
    const float* b0   = (const float*)d_in[5];
    const float* Ws1  = (const float*)d_in[6];
    const float* Wn1  = (const float*)d_in[7];
    const float* b1   = (const float*)d_in[8];

    int N = in_sizes[0] / D;   // 100000
    int E = in_sizes[1];       // 1600000

    float* out0 = (float*)d_out;
    float* a1   = out0 + (size_t)N * D;
    float* h2   = out0 + 2 * (size_t)N * D;

    int nd4 = N * (D / 4);
    int nb = (N + SCAN_BLK - 1) / SCAN_BLK;

    cudaFuncSetAttribute(sage_gemm_kernel,
                         cudaFuncAttributeMaxDynamicSharedMemorySize, SMEM_BYTES);

    copy_convert_kernel<<<(nd4 + 255) / 256, 256>>>(feat, out0, nd4, N);
    hist_kernel<<<(E + 255) / 256, 256>>>(dst, E);
    scan_blocks_kernel<<<nb, SCAN_BLK>>>(N);
    scan_add_kernel<<<(N + 255) / 256, 256>>>(N, E);
    fill_kernel<<<(E + 255) / 256, 256>>>(src, dst, E);

    gather_kernel<<<(N + 7) / 8, 256>>>(0, N);
    wconv_kernel<<<dim3((256 * 256 + 255) / 256, 2), 256>>>(Ws0, Wn0, Ws1, Wn1);

    dim3 ggrid(2, (N + 127) / 128);

    sage_gemm_kernel<<<ggrid, 256, SMEM_BYTES>>>(b0, a1, N, 0, 1);
    gather_kernel<<<(N + 7) / 8, 256>>>(1, N);
    sage_gemm_kernel<<<ggrid, 256, SMEM_BYTES>>>(b1, h2, N, 1, 0);
}

// round 14
// speedup vs baseline: 2.2101x; 1.2836x over previous
#include <cuda_runtime.h>
#include <cuda_fp16.h>
#include <cstddef>
#include <cstdint>

#define D 256
#define N_MAX 100000
#define E_MAX 1600000
#define SCAN_BLK 1024

// R2:  NEVER pass __device__ symbols as host-side kernel args (ATS shadow -> zeros).
// R8:  harness PTX targets compute_103 (no 'a') -> tcgen05 unavailable; legacy mma only.
// R10: all kernels saturate the chip -> single stream; per-kernel efficiency only.
// R11: GEMM at legacy-HMMA issue floor -> cut MMA count algorithmically.
// R12/13: fp16 precision-for-bandwidth validated (2.7e-4, 3.7x margin).

// ---- scratch (__device__ globals; allocation-free rule) ----
__device__ uint32_t g_feat_hi[(size_t)N_MAX * 128];  // fp16x2 words, [row][128]
__device__ uint32_t g_a1_hi[(size_t)N_MAX * 128];
__device__ uint32_t g_nhi[(size_t)N_MAX * 128];      // neigh aggregate, fp16
__device__ uint32_t g_wth[2][256 * 256];             // W^T: [n][512k as 256 words]
__device__ int g_cnt[N_MAX];
__device__ int g_off[N_MAX + 1];
__device__ int g_cursor[N_MAX];
__device__ int g_bsum[(N_MAX + SCAN_BLK - 1) / SCAN_BLK + 1];
__device__ int g_esrc[E_MAX];

// ---- fp16 helpers ----
__device__ __forceinline__ uint32_t pack2(float lo_elem, float hi_elem) {
    __half2 t = __floats2half2_rn(lo_elem, hi_elem);  // .x = low half
    return *reinterpret_cast<uint32_t*>(&t);
}
__device__ __forceinline__ void acc_word(float* a, uint32_t w) {
    float2 f = __half22float2(*reinterpret_cast<__half2*>(&w));
    a[0] += f.x; a[1] += f.y;
}

// ---------------------------------------------------------------------------
// copy feat -> out[0], convert to fp16 g_feat_hi, AND zero g_cnt (fused)
__global__ void copy_convert_kernel(const float* __restrict__ in,
                                    float* __restrict__ out, int n4, int N) {
    int i = blockIdx.x * blockDim.x + threadIdx.x;
    if (i < N) g_cnt[i] = 0;
    if (i >= n4) return;
    float4 v = ((const float4*)in)[i];
    ((float4*)out)[i] = v;
    *(uint2*)&g_feat_hi[(size_t)i * 2] =
        make_uint2(pack2(v.x, v.y), pack2(v.z, v.w));
}

__global__ void hist_kernel(const int* __restrict__ dst, int E) {
    int i = blockIdx.x * blockDim.x + threadIdx.x;
    if (i < E) atomicAdd(&g_cnt[dst[i]], 1);
}

__global__ void scan_blocks_kernel(int n) {
    __shared__ int sm[SCAN_BLK];
    int tid = threadIdx.x;
    int i = blockIdx.x * SCAN_BLK + tid;
    int v = (i < n) ? g_cnt[i] : 0;
    sm[tid] = v;
    __syncthreads();
#pragma unroll
    for (int off = 1; off < SCAN_BLK; off <<= 1) {
        int t = (tid >= off) ? sm[tid - off] : 0;
        __syncthreads();
        sm[tid] += t;
        __syncthreads();
    }
    if (i < n) g_off[i] = sm[tid] - v;
    if (tid == SCAN_BLK - 1) g_bsum[blockIdx.x] = sm[tid];
}

__global__ void scan_add_kernel(int n, int E) {
    __shared__ int pref;
    int g = (blockIdx.x * 256) >> 10;
    if (threadIdx.x < 32) {
        int s = 0;
        for (int j = threadIdx.x; j < g; j += 32) s += g_bsum[j];
#pragma unroll
        for (int o = 16; o; o >>= 1) s += __shfl_down_sync(0xFFFFFFFFu, s, o);
        if (threadIdx.x == 0) pref = s;
    }
    __syncthreads();
    int i = blockIdx.x * 256 + threadIdx.x;
    if (i < n) {
        int v = g_off[i] + pref;
        g_off[i] = v;
        g_cursor[i] = v;
    }
    if (i == 0) g_off[n] = E;
}

__global__ void fill_kernel(const int* __restrict__ src,
                            const int* __restrict__ dst, int E) {
    int e = blockIdx.x * blockDim.x + threadIdx.x;
    if (e < E) {
        int d = dst[e];
        int p = atomicAdd(&g_cursor[d], 1);
        g_esrc[p] = src[e];
    }
}

// transpose + fp16 weights, both layers in one launch
__global__ void wconv_kernel(const float* __restrict__ Ws0, const float* __restrict__ Wn0,
                             const float* __restrict__ Ws1, const float* __restrict__ Wn1) {
    int idx = blockIdx.x * blockDim.x + threadIdx.x;
    if (idx >= 256 * 256) return;
    int layer = blockIdx.y;
    const float* Ws = layer ? Ws1 : Ws0;
    const float* Wn = layer ? Wn1 : Wn0;
    int n = idx & 255;
    int wp = idx >> 8;
    int k0 = wp * 2, k1 = k0 + 1;
    float v0 = (k0 < 256) ? Ws[k0 * 256 + n] : Wn[(k0 - 256) * 256 + n];
    float v1 = (k1 < 256) ? Ws[k1 * 256 + n] : Wn[(k1 - 256) * 256 + n];
    g_wth[layer][n * 256 + wp] = pack2(v0, v1);
}

// ---------------------------------------------------------------------------
// Gather from fp16 rows (512B/edge): one warp per dst node, lane covers 8
// elems (one uint4). fp32 accumulate, fp16 output. layer selects DEVICE symbol.
__global__ void gather_kernel(int layer, int N) {
    int node = blockIdx.x * 8 + (threadIdx.x >> 5);
    if (node >= N) return;
    int lane = threadIdx.x & 31;

    const uint32_t* Xh = layer ? g_a1_hi : g_feat_hi;

    int beg = g_off[node];
    int end = g_off[node + 1];

    float a[8] = {};

    int i = beg;
    for (; i + 3 < end; i += 4) {
        int s0 = __ldg(g_esrc + i);
        int s1 = __ldg(g_esrc + i + 1);
        int s2 = __ldg(g_esrc + i + 2);
        int s3 = __ldg(g_esrc + i + 3);
        uint4 w0 = __ldg((const uint4*)(Xh + (size_t)s0 * 128) + lane);
        uint4 w1 = __ldg((const uint4*)(Xh + (size_t)s1 * 128) + lane);
        uint4 w2 = __ldg((const uint4*)(Xh + (size_t)s2 * 128) + lane);
        uint4 w3 = __ldg((const uint4*)(Xh + (size_t)s3 * 128) + lane);
        acc_word(a + 0, w0.x); acc_word(a + 2, w0.y);
        acc_word(a + 4, w0.z); acc_word(a + 6, w0.w);
        acc_word(a + 0, w1.x); acc_word(a + 2, w1.y);
        acc_word(a + 4, w1.z); acc_word(a + 6, w1.w);
        acc_word(a + 0, w2.x); acc_word(a + 2, w2.y);
        acc_word(a + 4, w2.z); acc_word(a + 6, w2.w);
        acc_word(a + 0, w3.x); acc_word(a + 2, w3.y);
        acc_word(a + 4, w3.z); acc_word(a + 6, w3.w);
    }
    for (; i < end; ++i) {
        int s0 = __ldg(g_esrc + i);
        uint4 w0 = __ldg((const uint4*)(Xh + (size_t)s0 * 128) + lane);
        acc_word(a + 0, w0.x); acc_word(a + 2, w0.y);
        acc_word(a + 4, w0.z); acc_word(a + 6, w0.w);
    }

    float inv = (end > beg) ? (1.0f / (float)(end - beg)) : 0.f;
    uint4 ow;
    ow.x = pack2(a[0] * inv, a[1] * inv);
    ow.y = pack2(a[2] * inv, a[3] * inv);
    ow.z = pack2(a[4] * inv, a[5] * inv);
    ow.w = pack2(a[6] * inv, a[7] * inv);
    *((uint4*)(g_nhi + (size_t)node * 128) + lane) = ow;
}

// ---------------------------------------------------------------------------
// fp16 single-product tensor GEMM: out[M,256] = [Xh | NH] @ Wt^T + bias.
// fp32 accum. CTA 128x128, warp 32x64. Per warp k32-iter: 12 LDSM + 32 MMA.
#define T_STR 20
#define SA_SZ (128 * T_STR)
#define SB_SZ (128 * T_STR)
#define SMEM_WORDS (2 * (SA_SZ + SB_SZ))
#define SMEM_BYTES (SMEM_WORDS * 4)

__device__ __forceinline__ void cp_async16(void* s, const void* g, bool pred) {
    uint32_t sa = (uint32_t)__cvta_generic_to_shared(s);
    int sz = pred ? 16 : 0;
    asm volatile("cp.async.cg.shared.global [%0], [%1], 16, %2;"
                 :: "r"(sa), "l"(g), "r"(sz) : "memory");
}

__device__ __forceinline__ void mma_f16(float* c, const uint32_t* a, const uint32_t* b) {
    asm volatile(
        "mma.sync.aligned.m16n8k16.row.col.f32.f16.f16.f32 "
        "{%0,%1,%2,%3}, {%4,%5,%6,%7}, {%8,%9}, {%0,%1,%2,%3};"
        : "+f"(c[0]), "+f"(c[1]), "+f"(c[2]), "+f"(c[3])
        : "r"(a[0]), "r"(a[1]), "r"(a[2]), "r"(a[3]), "r"(b[0]), "r"(b[1]));
}

__device__ __forceinline__ void ldsm_x4(uint32_t* r, uint32_t addr) {
    asm volatile("ldmatrix.sync.aligned.m8n8.x4.shared.b16 {%0,%1,%2,%3}, [%4];"
                 : "=r"(r[0]), "=r"(r[1]), "=r"(r[2]), "=r"(r[3]) : "r"(addr));
}

__global__ void __launch_bounds__(256, 2) sage_gemm_kernel(
    const float* __restrict__ bias,
    float* __restrict__ out,
    int M, int layer, int do_relu) {
    extern __shared__ uint32_t smem[];
    uint32_t* sA = smem;                        // 2 stages x [128][T_STR]
    uint32_t* sB = smem + 2 * SA_SZ;            // 2 stages x [128][T_STR]
    const uint32_t smem_u32 = (uint32_t)__cvta_generic_to_shared(smem);

    const int tid = threadIdx.x;
    const int lane = tid & 31;
    const int wid = tid >> 5;
    const int wm = wid >> 1;          // 0..3  (m32 each)
    const int wn = wid & 1;           // 0..1  (n64 each)
    const int bm = blockIdx.y * 128;
    const int bn = blockIdx.x * 128;

    const uint32_t* Xh = layer ? g_a1_hi : g_feat_hi;
    const uint32_t* Wh = g_wth[layer];

    float acc[2][8][4] = {};

    auto load_tile = [&](int it, int buf) {
        const uint32_t* A = (it < 8) ? Xh : (const uint32_t*)g_nhi;
        int klw = (it & 7) * 16;
        uint32_t* dA = sA + buf * SA_SZ;
        uint32_t* dB = sB + buf * SB_SZ;
#pragma unroll
        for (int i = 0; i < 2; ++i) {            // A: 128 rows x 4 chunks
            int ci = i * 256 + tid;
            int row = ci >> 2, ch = ci & 3;
            int grow = bm + row;
            bool ok = grow < M;
            size_t off = (size_t)(ok ? grow : (M - 1)) * 128 + klw + ch * 4;
            cp_async16(dA + row * T_STR + ch * 4, A + off, ok);
        }
#pragma unroll
        for (int i = 0; i < 2; ++i) {            // B: 128 rows x 4 chunks
            int ci = i * 256 + tid;
            int row = ci >> 2, ch = ci & 3;
            size_t off = (size_t)(bn + row) * 256 + it * 16 + ch * 4;
            cp_async16(dB + row * T_STR + ch * 4, Wh + off, true);
        }
    };

    load_tile(0, 0);
    asm volatile("cp.async.commit_group;" ::: "memory");

    const int a_r = wm * 32 + (lane & 15);
    const int a_w = (lane >> 4) << 2;
    const int b_r = wn * 64 + (lane & 7) + ((lane >> 4) << 3);
    const int b_w = ((lane >> 3) & 1) << 2;

    const int K_ITERS = 512 / 32;  // 16
#pragma unroll 1
    for (int it = 0; it < K_ITERS; ++it) {
        if (it + 1 < K_ITERS) {
            load_tile(it + 1, (it + 1) & 1);
            asm volatile("cp.async.commit_group;" ::: "memory");
            asm volatile("cp.async.wait_group 1;" ::: "memory");
        } else {
            asm volatile("cp.async.wait_group 0;" ::: "memory");
        }
        __syncthreads();

        const uint32_t aB = smem_u32 + ((it & 1) * SA_SZ) * 4;
        const uint32_t bB = smem_u32 + (2 * SA_SZ + (it & 1) * SB_SZ) * 4;

#pragma unroll
        for (int ks = 0; ks < 2; ++ks) {
            uint32_t ah[2][4];
#pragma unroll
            for (int mt = 0; mt < 2; ++mt) {
                uint32_t off = (uint32_t)(((a_r + mt * 16) * T_STR + a_w + ks * 8) * 4);
                ldsm_x4(ah[mt], aB + off);
            }
#pragma unroll
            for (int np = 0; np < 4; ++np) {
                uint32_t off = (uint32_t)(((b_r + np * 16) * T_STR + b_w + ks * 8) * 4);
                uint32_t th[4];
                ldsm_x4(th, bB + off);
#pragma unroll
                for (int mt = 0; mt < 2; ++mt) {
                    mma_f16(acc[mt][np * 2 + 0], ah[mt], th + 0);
                    mma_f16(acc[mt][np * 2 + 1], ah[mt], th + 2);
                }
            }
        }
        __syncthreads();
    }

    // ---- epilogue: bias (+relu); layer 0 also writes a1 fp16 ----
#pragma unroll
    for (int mt = 0; mt < 2; ++mt) {
        int r0 = bm + wm * 32 + mt * 16 + (lane >> 2);
#pragma unroll
        for (int nt = 0; nt < 8; ++nt) {
            int cc = bn + wn * 64 + nt * 8 + (lane & 3) * 2;
            float bx = __ldg(bias + cc);
            float by = __ldg(bias + cc + 1);
            float2 v0, v1;
            v0.x = acc[mt][nt][0] + bx; v0.y = acc[mt][nt][1] + by;
            v1.x = acc[mt][nt][2] + bx; v1.y = acc[mt][nt][3] + by;
            if (do_relu) {
                v0.x = fmaxf(v0.x, 0.f); v0.y = fmaxf(v0.y, 0.f);
                v1.x = fmaxf(v1.x, 0.f); v1.y = fmaxf(v1.y, 0.f);
            }
            if (r0 < M) {
                *(float2*)(out + (size_t)r0 * 256 + cc) = v0;
                if (do_relu)
                    g_a1_hi[(size_t)r0 * 128 + (cc >> 1)] = pack2(v0.x, v0.y);
            }
            if (r0 + 8 < M) {
                *(float2*)(out + (size_t)(r0 + 8) * 256 + cc) = v1;
                if (do_relu)
                    g_a1_hi[(size_t)(r0 + 8) * 128 + (cc >> 1)] = pack2(v1.x, v1.y);
            }
        }
    }
}

// ---------------------------------------------------------------------------
extern "C" void kernel_launch(void* const* d_in, const int* in_sizes, int n_in,
                              void* d_out, int out_size) {
    const float* feat = (const float*)d_in[0];
    const int*   src  = (const int*)d_in[1];
    const int*   dst  = (const int*)d_in[2];
    const float* Ws0  = (const float*)d_in[3];
    const float* Wn0  = (const float*)d_in[4];
    const float* b0   = (const float*)d_in[5];
    const float* Ws1  = (const float*)d_in[6];
    const float* Wn1  = (const float*)d_in[7];
    const float* b1   = (const float*)d_in[8];

    int N = in_sizes[0] / D;   // 100000
    int E = in_sizes[1];       // 1600000

    float* out0 = (float*)d_out;
    float* a1   = out0 + (size_t)N * D;
    float* h2   = out0 + 2 * (size_t)N * D;

    int nd4 = N * (D / 4);
    int nb = (N + SCAN_BLK - 1) / SCAN_BLK;

    cudaFuncSetAttribute(sage_gemm_kernel,
                         cudaFuncAttributeMaxDynamicSharedMemorySize, SMEM_BYTES);

    copy_convert_kernel<<<(nd4 + 255) / 256, 256>>>(feat, out0, nd4, N);
    hist_kernel<<<(E + 255) / 256, 256>>>(dst, E);
    scan_blocks_kernel<<<nb, SCAN_BLK>>>(N);
    scan_add_kernel<<<(N + 255) / 256, 256>>>(N, E);
    fill_kernel<<<(E + 255) / 256, 256>>>(src, dst, E);

    gather_kernel<<<(N + 7) / 8, 256>>>(0, N);
    wconv_kernel<<<dim3((256 * 256 + 255) / 256, 2), 256>>>(Ws0, Wn0, Ws1, Wn1);

    dim3 ggrid(2, (N + 127) / 128);

    sage_gemm_kernel<<<ggrid, 256, SMEM_BYTES>>>(b0, a1, N, 0, 1);
    gather_kernel<<<(N + 7) / 8, 256>>>(1, N);
    sage_gemm_kernel<<<ggrid, 256, SMEM_BYTES>>>(b1, h2, N, 1, 0);
}

// round 15
// speedup vs baseline: 2.3370x; 1.0574x over previous
#include <cuda_runtime.h>
#include <cuda_fp16.h>
#include <cstddef>
#include <cstdint>

#define D 256
#define N_MAX 100000
#define E_MAX 1600000
#define SCAN_BLK 1024

// R2:  NEVER pass __device__ symbols as host-side kernel args (ATS shadow -> zeros).
// R8:  harness PTX targets compute_103 (no 'a') -> tcgen05 unavailable; legacy mma only.
// R10: all kernels saturate the chip -> single stream; per-kernel efficiency only.
// R11: GEMM at legacy-HMMA issue floor -> cut MMA count algorithmically.
// R12-14: fp16 precision-for-bandwidth validated (3.64e-4, 2.7x margin; floor reached).

// ---- scratch (__device__ globals; allocation-free rule) ----
__device__ uint32_t g_feat_hi[(size_t)N_MAX * 128];  // fp16x2 words, [row][128]
__device__ uint32_t g_a1_hi[(size_t)N_MAX * 128];
__device__ uint32_t g_nhi[(size_t)N_MAX * 128];      // neigh aggregate, fp16
__device__ uint32_t g_wth[2][256 * 256];             // W^T: [n][512k as 256 words]
__device__ int g_cnt[N_MAX];
__device__ int g_off[N_MAX + 1];
__device__ int g_cursor[N_MAX];
__device__ int g_bsum[(N_MAX + SCAN_BLK - 1) / SCAN_BLK + 1];
__device__ int g_esrc[E_MAX];

// ---- fp16 helpers ----
__device__ __forceinline__ uint32_t pack2(float lo_elem, float hi_elem) {
    __half2 t = __floats2half2_rn(lo_elem, hi_elem);  // .x = low half
    return *reinterpret_cast<uint32_t*>(&t);
}
__device__ __forceinline__ void acc_word(float* a, uint32_t w) {
    float2 f = __half22float2(*reinterpret_cast<__half2*>(&w));
    a[0] += f.x; a[1] += f.y;
}

// ---------------------------------------------------------------------------
// copy feat -> out[0], convert to fp16 g_feat_hi, AND zero g_cnt (fused)
__global__ void copy_convert_kernel(const float* __restrict__ in,
                                    float* __restrict__ out, int n4, int N) {
    int i = blockIdx.x * blockDim.x + threadIdx.x;
    if (i < N) g_cnt[i] = 0;
    if (i >= n4) return;
    float4 v = ((const float4*)in)[i];
    ((float4*)out)[i] = v;
    *(uint2*)&g_feat_hi[(size_t)i * 2] =
        make_uint2(pack2(v.x, v.y), pack2(v.z, v.w));
}

__global__ void hist_kernel(const int* __restrict__ dst, int E) {
    int i = blockIdx.x * blockDim.x + threadIdx.x;
    if (i < E) atomicAdd(&g_cnt[dst[i]], 1);
}

__global__ void scan_blocks_kernel(int n) {
    __shared__ int sm[SCAN_BLK];
    int tid = threadIdx.x;
    int i = blockIdx.x * SCAN_BLK + tid;
    int v = (i < n) ? g_cnt[i] : 0;
    sm[tid] = v;
    __syncthreads();
#pragma unroll
    for (int off = 1; off < SCAN_BLK; off <<= 1) {
        int t = (tid >= off) ? sm[tid - off] : 0;
        __syncthreads();
        sm[tid] += t;
        __syncthreads();
    }
    if (i < n) g_off[i] = sm[tid] - v;
    if (tid == SCAN_BLK - 1) g_bsum[blockIdx.x] = sm[tid];
}

__global__ void scan_add_kernel(int n, int E) {
    __shared__ int pref;
    int g = (blockIdx.x * 256) >> 10;
    if (threadIdx.x < 32) {
        int s = 0;
        for (int j = threadIdx.x; j < g; j += 32) s += g_bsum[j];
#pragma unroll
        for (int o = 16; o; o >>= 1) s += __shfl_down_sync(0xFFFFFFFFu, s, o);
        if (threadIdx.x == 0) pref = s;
    }
    __syncthreads();
    int i = blockIdx.x * 256 + threadIdx.x;
    if (i < n) {
        int v = g_off[i] + pref;
        g_off[i] = v;
        g_cursor[i] = v;
    }
    if (i == 0) g_off[n] = E;
}

__global__ void fill_kernel(const int* __restrict__ src,
                            const int* __restrict__ dst, int E) {
    int e = blockIdx.x * blockDim.x + threadIdx.x;
    if (e < E) {
        int d = dst[e];
        int p = atomicAdd(&g_cursor[d], 1);
        g_esrc[p] = src[e];
    }
}

// transpose + fp16 weights, both layers in one launch
__global__ void wconv_kernel(const float* __restrict__ Ws0, const float* __restrict__ Wn0,
                             const float* __restrict__ Ws1, const float* __restrict__ Wn1) {
    int idx = blockIdx.x * blockDim.x + threadIdx.x;
    if (idx >= 256 * 256) return;
    int layer = blockIdx.y;
    const float* Ws = layer ? Ws1 : Ws0;
    const float* Wn = layer ? Wn1 : Wn0;
    int n = idx & 255;
    int wp = idx >> 8;
    int k0 = wp * 2, k1 = k0 + 1;
    float v0 = (k0 < 256) ? Ws[k0 * 256 + n] : Wn[(k0 - 256) * 256 + n];
    float v1 = (k1 < 256) ? Ws[k1 * 256 + n] : Wn[(k1 - 256) * 256 + n];
    g_wth[layer][n * 256 + wp] = pack2(v0, v1);
}

// ---------------------------------------------------------------------------
// Gather from fp16 rows (512B/edge): one warp per dst node, lane covers 8
// elems (one uint4). fp32 accumulate, fp16 output. layer selects DEVICE symbol.
__global__ void gather_kernel(int layer, int N) {
    int node = blockIdx.x * 8 + (threadIdx.x >> 5);
    if (node >= N) return;
    int lane = threadIdx.x & 31;

    const uint32_t* Xh = layer ? g_a1_hi : g_feat_hi;

    int beg = g_off[node];
    int end = g_off[node + 1];

    float a[8] = {};

    int i = beg;
    for (; i + 3 < end; i += 4) {
        int s0 = __ldg(g_esrc + i);
        int s1 = __ldg(g_esrc + i + 1);
        int s2 = __ldg(g_esrc + i + 2);
        int s3 = __ldg(g_esrc + i + 3);
        uint4 w0 = __ldg((const uint4*)(Xh + (size_t)s0 * 128) + lane);
        uint4 w1 = __ldg((const uint4*)(Xh + (size_t)s1 * 128) + lane);
        uint4 w2 = __ldg((const uint4*)(Xh + (size_t)s2 * 128) + lane);
        uint4 w3 = __ldg((const uint4*)(Xh + (size_t)s3 * 128) + lane);
        acc_word(a + 0, w0.x); acc_word(a + 2, w0.y);
        acc_word(a + 4, w0.z); acc_word(a + 6, w0.w);
        acc_word(a + 0, w1.x); acc_word(a + 2, w1.y);
        acc_word(a + 4, w1.z); acc_word(a + 6, w1.w);
        acc_word(a + 0, w2.x); acc_word(a + 2, w2.y);
        acc_word(a + 4, w2.z); acc_word(a + 6, w2.w);
        acc_word(a + 0, w3.x); acc_word(a + 2, w3.y);
        acc_word(a + 4, w3.z); acc_word(a + 6, w3.w);
    }
    for (; i < end; ++i) {
        int s0 = __ldg(g_esrc + i);
        uint4 w0 = __ldg((const uint4*)(Xh + (size_t)s0 * 128) + lane);
        acc_word(a + 0, w0.x); acc_word(a + 2, w0.y);
        acc_word(a + 4, w0.z); acc_word(a + 6, w0.w);
    }

    float inv = (end > beg) ? (1.0f / (float)(end - beg)) : 0.f;
    uint4 ow;
    ow.x = pack2(a[0] * inv, a[1] * inv);
    ow.y = pack2(a[2] * inv, a[3] * inv);
    ow.z = pack2(a[4] * inv, a[5] * inv);
    ow.w = pack2(a[6] * inv, a[7] * inv);
    *((uint4*)(g_nhi + (size_t)node * 128) + lane) = ow;
}

// ---------------------------------------------------------------------------
// fp16 tensor GEMM: out[M,256] = [Xh | NH] @ Wt^T + bias, fp32 accum.
// CTA 128x128, warp 32x64, BK=64 stages (8 iters, half the barriers of BK=32).
#define T_STR 36
#define SA_SZ (128 * T_STR)
#define SB_SZ (128 * T_STR)
#define SMEM_WORDS (2 * (SA_SZ + SB_SZ))
#define SMEM_BYTES (SMEM_WORDS * 4)

__device__ __forceinline__ void cp_async16(void* s, const void* g, bool pred) {
    uint32_t sa = (uint32_t)__cvta_generic_to_shared(s);
    int sz = pred ? 16 : 0;
    asm volatile("cp.async.cg.shared.global [%0], [%1], 16, %2;"
                 :: "r"(sa), "l"(g), "r"(sz) : "memory");
}

__device__ __forceinline__ void mma_f16(float* c, const uint32_t* a, const uint32_t* b) {
    asm volatile(
        "mma.sync.aligned.m16n8k16.row.col.f32.f16.f16.f32 "
        "{%0,%1,%2,%3}, {%4,%5,%6,%7}, {%8,%9}, {%0,%1,%2,%3};"
        : "+f"(c[0]), "+f"(c[1]), "+f"(c[2]), "+f"(c[3])
        : "r"(a[0]), "r"(a[1]), "r"(a[2]), "r"(a[3]), "r"(b[0]), "r"(b[1]));
}

__device__ __forceinline__ void ldsm_x4(uint32_t* r, uint32_t addr) {
    asm volatile("ldmatrix.sync.aligned.m8n8.x4.shared.b16 {%0,%1,%2,%3}, [%4];"
                 : "=r"(r[0]), "=r"(r[1]), "=r"(r[2]), "=r"(r[3]) : "r"(addr));
}

__global__ void __launch_bounds__(256, 2) sage_gemm_kernel(
    const float* __restrict__ bias,
    float* __restrict__ out,
    int M, int layer, int do_relu) {
    extern __shared__ uint32_t smem[];
    uint32_t* sA = smem;                        // 2 stages x [128][T_STR]
    uint32_t* sB = smem + 2 * SA_SZ;            // 2 stages x [128][T_STR]
    const uint32_t smem_u32 = (uint32_t)__cvta_generic_to_shared(smem);

    const int tid = threadIdx.x;
    const int lane = tid & 31;
    const int wid = tid >> 5;
    const int wm = wid >> 1;          // 0..3  (m32 each)
    const int wn = wid & 1;           // 0..1  (n64 each)
    const int bm = blockIdx.y * 128;
    const int bn = blockIdx.x * 128;

    const uint32_t* Xh = layer ? g_a1_hi : g_feat_hi;
    const uint32_t* Wh = g_wth[layer];

    float acc[2][8][4] = {};

    // stage = 64 k-halves = 32 words per row; 8 chunks of 16B per row
    auto load_tile = [&](int it, int buf) {
        const uint32_t* A = (it < 4) ? Xh : (const uint32_t*)g_nhi;
        int klw = (it & 3) * 32;
        uint32_t* dA = sA + buf * SA_SZ;
        uint32_t* dB = sB + buf * SB_SZ;
#pragma unroll
        for (int i = 0; i < 4; ++i) {            // A: 128 rows x 8 chunks
            int ci = i * 256 + tid;
            int row = ci >> 3, ch = ci & 7;
            int grow = bm + row;
            bool ok = grow < M;
            size_t off = (size_t)(ok ? grow : (M - 1)) * 128 + klw + ch * 4;
            cp_async16(dA + row * T_STR + ch * 4, A + off, ok);
        }
#pragma unroll
        for (int i = 0; i < 4; ++i) {            // B: 128 rows x 8 chunks
            int ci = i * 256 + tid;
            int row = ci >> 3, ch = ci & 7;
            size_t off = (size_t)(bn + row) * 256 + it * 32 + ch * 4;
            cp_async16(dB + row * T_STR + ch * 4, Wh + off, true);
        }
    };

    load_tile(0, 0);
    asm volatile("cp.async.commit_group;" ::: "memory");

    const int a_r = wm * 32 + (lane & 15);
    const int a_w = (lane >> 4) << 2;
    const int b_r = wn * 64 + (lane & 7) + ((lane >> 4) << 3);
    const int b_w = ((lane >> 3) & 1) << 2;

    const int K_ITERS = 512 / 64;  // 8
#pragma unroll 1
    for (int it = 0; it < K_ITERS; ++it) {
        if (it + 1 < K_ITERS) {
            load_tile(it + 1, (it + 1) & 1);
            asm volatile("cp.async.commit_group;" ::: "memory");
            asm volatile("cp.async.wait_group 1;" ::: "memory");
        } else {
            asm volatile("cp.async.wait_group 0;" ::: "memory");
        }
        __syncthreads();

        const uint32_t aB = smem_u32 + ((it & 1) * SA_SZ) * 4;
        const uint32_t bB = smem_u32 + (2 * SA_SZ + (it & 1) * SB_SZ) * 4;

#pragma unroll
        for (int ks = 0; ks < 4; ++ks) {
            uint32_t ah[2][4];
#pragma unroll
            for (int mt = 0; mt < 2; ++mt) {
                uint32_t off = (uint32_t)(((a_r + mt * 16) * T_STR + a_w + ks * 8) * 4);
                ldsm_x4(ah[mt], aB + off);
            }
#pragma unroll
            for (int np = 0; np < 4; ++np) {
                uint32_t off = (uint32_t)(((b_r + np * 16) * T_STR + b_w + ks * 8) * 4);
                uint32_t th[4];
                ldsm_x4(th, bB + off);
#pragma unroll
                for (int mt = 0; mt < 2; ++mt) {
                    mma_f16(acc[mt][np * 2 + 0], ah[mt], th + 0);
                    mma_f16(acc[mt][np * 2 + 1], ah[mt], th + 2);
                }
            }
        }
        __syncthreads();
    }

    // ---- epilogue: bias (+relu); layer 0 also writes a1 fp16 ----
#pragma unroll
    for (int mt = 0; mt < 2; ++mt) {
        int r0 = bm + wm * 32 + mt * 16 + (lane >> 2);
#pragma unroll
        for (int nt = 0; nt < 8; ++nt) {
            int cc = bn + wn * 64 + nt * 8 + (lane & 3) * 2;
            float bx = __ldg(bias + cc);
            float by = __ldg(bias + cc + 1);
            float2 v0, v1;
            v0.x = acc[mt][nt][0] + bx; v0.y = acc[mt][nt][1] + by;
            v1.x = acc[mt][nt][2] + bx; v1.y = acc[mt][nt][3] + by;
            if (do_relu) {
                v0.x = fmaxf(v0.x, 0.f); v0.y = fmaxf(v0.y, 0.f);
                v1.x = fmaxf(v1.x, 0.f); v1.y = fmaxf(v1.y, 0.f);
            }
            if (r0 < M) {
                *(float2*)(out + (size_t)r0 * 256 + cc) = v0;
                if (do_relu)
                    g_a1_hi[(size_t)r0 * 128 + (cc >> 1)] = pack2(v0.x, v0.y);
            }
            if (r0 + 8 < M) {
                *(float2*)(out + (size_t)(r0 + 8) * 256 + cc) = v1;
                if (do_relu)
                    g_a1_hi[(size_t)(r0 + 8) * 128 + (cc >> 1)] = pack2(v1.x, v1.y);
            }
        }
    }
}

// ---------------------------------------------------------------------------
extern "C" void kernel_launch(void* const* d_in, const int* in_sizes, int n_in,
                              void* d_out, int out_size) {
    const float* feat = (const float*)d_in[0];
    const int*   src  = (const int*)d_in[1];
    const int*   dst  = (const int*)d_in[2];
    const float* Ws0  = (const float*)d_in[3];
    const float* Wn0  = (const float*)d_in[4];
    const float* b0   = (const float*)d_in[5];
    const float* Ws1  = (const float*)d_in[6];
    const float* Wn1  = (const float*)d_in[7];
    const float* b1   = (const float*)d_in[8];

    int N = in_sizes[0] / D;   // 100000
    int E = in_sizes[1];       // 1600000

    float* out0 = (float*)d_out;
    float* a1   = out0 + (size_t)N * D;
    float* h2   = out0 + 2 * (size_t)N * D;

    int nd4 = N * (D / 4);
    int nb = (N + SCAN_BLK - 1) / SCAN_BLK;

    cudaFuncSetAttribute(sage_gemm_kernel,
                         cudaFuncAttributeMaxDynamicSharedMemorySize, SMEM_BYTES);

    copy_convert_kernel<<<(nd4 + 255) / 256, 256>>>(feat, out0, nd4, N);
    hist_kernel<<<(E + 255) / 256, 256>>>(dst, E);
    scan_blocks_kernel<<<nb, SCAN_BLK>>>(N);
    scan_add_kernel<<<(N + 255) / 256, 256>>>(N, E);
    fill_kernel<<<(E + 255) / 256, 256>>>(src, dst, E);

    gather_kernel<<<(N + 7) / 8, 256>>>(0, N);
    wconv_kernel<<<dim3((256 * 256 + 255) / 256, 2), 256>>>(Ws0, Wn0, Ws1, Wn1);

    dim3 ggrid(2, (N + 127) / 128);

    sage_gemm_kernel<<<ggrid, 256, SMEM_BYTES>>>(b0, a1, N, 0, 1);
    gather_kernel<<<(N + 7) / 8, 256>>>(1, N);
    sage_gemm_kernel<<<ggrid, 256, SMEM_BYTES>>>(b1, h2, N, 1, 0);
}

// round 16
// speedup vs baseline: 2.3544x; 1.0074x over previous
#include <cuda_runtime.h>
#include <cuda_fp16.h>
#include <cstddef>
#include <cstdint>

#define D 256
#define N_MAX 100000
#define E_MAX 1600000
#define SCAN_BLK 1024

// R2:  NEVER pass __device__ symbols as host-side kernel args (ATS shadow -> zeros).
// R8:  harness PTX targets compute_103 (no 'a') -> tcgen05 unavailable; legacy mma only.
// R10: all kernels saturate the chip -> single stream; per-kernel efficiency only.
// R11: GEMM at legacy-HMMA issue floor -> cut MMA count algorithmically.
// R12-14: fp16 precision-for-bandwidth validated (3.64e-4, 2.7x margin; floor reached).
// R15: BK=64 staging validated (-21.7us).

// ---- scratch (__device__ globals; allocation-free rule) ----
__device__ uint32_t g_feat_hi[(size_t)N_MAX * 128];  // fp16x2 words, [row][128]
__device__ uint32_t g_a1_hi[(size_t)N_MAX * 128];
__device__ uint32_t g_nhi[(size_t)N_MAX * 128];      // neigh aggregate, fp16
__device__ uint32_t g_wth[2][256 * 256];             // W^T: [n][512k as 256 words]
__device__ int g_cnt[N_MAX];
__device__ int g_off[N_MAX + 1];
__device__ int g_cursor[N_MAX];
__device__ int g_bsum[(N_MAX + SCAN_BLK - 1) / SCAN_BLK + 1];
__device__ int g_esrc[E_MAX];

// ---- fp16 helpers ----
__device__ __forceinline__ uint32_t pack2(float lo_elem, float hi_elem) {
    __half2 t = __floats2half2_rn(lo_elem, hi_elem);  // .x = low half
    return *reinterpret_cast<uint32_t*>(&t);
}
__device__ __forceinline__ void acc_word(float* a, uint32_t w) {
    float2 f = __half22float2(*reinterpret_cast<__half2*>(&w));
    a[0] += f.x; a[1] += f.y;
}

// ---------------------------------------------------------------------------
// Fused prologue: copy feat -> out[0], convert feat to fp16, zero g_cnt,
// AND transpose+convert both layers' weights (first 131072 threads).
__global__ void copy_convert_kernel(const float* __restrict__ in,
                                    float* __restrict__ out, int n4, int N,
                                    const float* __restrict__ Ws0,
                                    const float* __restrict__ Wn0,
                                    const float* __restrict__ Ws1,
                                    const float* __restrict__ Wn1) {
    int i = blockIdx.x * blockDim.x + threadIdx.x;
    if (i < N) g_cnt[i] = 0;
    if (i < 2 * 256 * 256) {
        int layer = i >> 16;
        int idx = i & 65535;
        const float* Ws = layer ? Ws1 : Ws0;
        const float* Wn = layer ? Wn1 : Wn0;
        int n = idx & 255;
        int wp = idx >> 8;
        int k0 = wp * 2, k1 = k0 + 1;
        float v0 = (k0 < 256) ? Ws[k0 * 256 + n] : Wn[(k0 - 256) * 256 + n];
        float v1 = (k1 < 256) ? Ws[k1 * 256 + n] : Wn[(k1 - 256) * 256 + n];
        g_wth[layer][n * 256 + wp] = pack2(v0, v1);
    }
    if (i >= n4) return;
    float4 v = ((const float4*)in)[i];
    ((float4*)out)[i] = v;
    *(uint2*)&g_feat_hi[(size_t)i * 2] =
        make_uint2(pack2(v.x, v.y), pack2(v.z, v.w));
}

__global__ void hist_kernel(const int* __restrict__ dst, int E) {
    int i = blockIdx.x * blockDim.x + threadIdx.x;
    if (i < E) atomicAdd(&g_cnt[dst[i]], 1);
}

__global__ void scan_blocks_kernel(int n) {
    __shared__ int sm[SCAN_BLK];
    int tid = threadIdx.x;
    int i = blockIdx.x * SCAN_BLK + tid;
    int v = (i < n) ? g_cnt[i] : 0;
    sm[tid] = v;
    __syncthreads();
#pragma unroll
    for (int off = 1; off < SCAN_BLK; off <<= 1) {
        int t = (tid >= off) ? sm[tid - off] : 0;
        __syncthreads();
        sm[tid] += t;
        __syncthreads();
    }
    if (i < n) g_off[i] = sm[tid] - v;
    if (tid == SCAN_BLK - 1) g_bsum[blockIdx.x] = sm[tid];
}

__global__ void scan_add_kernel(int n, int E) {
    __shared__ int pref;
    int g = (blockIdx.x * 256) >> 10;
    if (threadIdx.x < 32) {
        int s = 0;
        for (int j = threadIdx.x; j < g; j += 32) s += g_bsum[j];
#pragma unroll
        for (int o = 16; o; o >>= 1) s += __shfl_down_sync(0xFFFFFFFFu, s, o);
        if (threadIdx.x == 0) pref = s;
    }
    __syncthreads();
    int i = blockIdx.x * 256 + threadIdx.x;
    if (i < n) {
        int v = g_off[i] + pref;
        g_off[i] = v;
        g_cursor[i] = v;
    }
    if (i == 0) g_off[n] = E;
}

__global__ void fill_kernel(const int* __restrict__ src,
                            const int* __restrict__ dst, int E) {
    int e = blockIdx.x * blockDim.x + threadIdx.x;
    if (e < E) {
        int d = dst[e];
        int p = atomicAdd(&g_cursor[d], 1);
        g_esrc[p] = src[e];
    }
}

// ---------------------------------------------------------------------------
// Gather from fp16 rows (512B/edge): one warp per dst node, lane covers 8
// elems (one uint4). fp32 accumulate, fp16 output. layer selects DEVICE symbol.
__global__ void gather_kernel(int layer, int N) {
    int node = blockIdx.x * 8 + (threadIdx.x >> 5);
    if (node >= N) return;
    int lane = threadIdx.x & 31;

    const uint32_t* Xh = layer ? g_a1_hi : g_feat_hi;

    int beg = g_off[node];
    int end = g_off[node + 1];

    float a[8] = {};

    int i = beg;
    for (; i + 3 < end; i += 4) {
        int s0 = __ldg(g_esrc + i);
        int s1 = __ldg(g_esrc + i + 1);
        int s2 = __ldg(g_esrc + i + 2);
        int s3 = __ldg(g_esrc + i + 3);
        uint4 w0 = __ldg((const uint4*)(Xh + (size_t)s0 * 128) + lane);
        uint4 w1 = __ldg((const uint4*)(Xh + (size_t)s1 * 128) + lane);
        uint4 w2 = __ldg((const uint4*)(Xh + (size_t)s2 * 128) + lane);
        uint4 w3 = __ldg((const uint4*)(Xh + (size_t)s3 * 128) + lane);
        acc_word(a + 0, w0.x); acc_word(a + 2, w0.y);
        acc_word(a + 4, w0.z); acc_word(a + 6, w0.w);
        acc_word(a + 0, w1.x); acc_word(a + 2, w1.y);
        acc_word(a + 4, w1.z); acc_word(a + 6, w1.w);
        acc_word(a + 0, w2.x); acc_word(a + 2, w2.y);
        acc_word(a + 4, w2.z); acc_word(a + 6, w2.w);
        acc_word(a + 0, w3.x); acc_word(a + 2, w3.y);
        acc_word(a + 4, w3.z); acc_word(a + 6, w3.w);
    }
    for (; i < end; ++i) {
        int s0 = __ldg(g_esrc + i);
        uint4 w0 = __ldg((const uint4*)(Xh + (size_t)s0 * 128) + lane);
        acc_word(a + 0, w0.x); acc_word(a + 2, w0.y);
        acc_word(a + 4, w0.z); acc_word(a + 6, w0.w);
    }

    float inv = (end > beg) ? (1.0f / (float)(end - beg)) : 0.f;
    uint4 ow;
    ow.x = pack2(a[0] * inv, a[1] * inv);
    ow.y = pack2(a[2] * inv, a[3] * inv);
    ow.z = pack2(a[4] * inv, a[5] * inv);
    ow.w = pack2(a[6] * inv, a[7] * inv);
    *((uint4*)(g_nhi + (size_t)node * 128) + lane) = ow;
}

// ---------------------------------------------------------------------------
// fp16 tensor GEMM: out[M,256] = [Xh | NH] @ Wt^T + bias, fp32 accum.
// CTA 128x128, warp 32x64, BK=64 stages, ONE __syncthreads per iteration.
#define T_STR 36
#define SA_SZ (128 * T_STR)
#define SB_SZ (128 * T_STR)
#define SMEM_WORDS (2 * (SA_SZ + SB_SZ))
#define SMEM_BYTES (SMEM_WORDS * 4)

__device__ __forceinline__ void cp_async16(void* s, const void* g, bool pred) {
    uint32_t sa = (uint32_t)__cvta_generic_to_shared(s);
    int sz = pred ? 16 : 0;
    asm volatile("cp.async.cg.shared.global [%0], [%1], 16, %2;"
                 :: "r"(sa), "l"(g), "r"(sz) : "memory");
}

__device__ __forceinline__ void mma_f16(float* c, const uint32_t* a, const uint32_t* b) {
    asm volatile(
        "mma.sync.aligned.m16n8k16.row.col.f32.f16.f16.f32 "
        "{%0,%1,%2,%3}, {%4,%5,%6,%7}, {%8,%9}, {%0,%1,%2,%3};"
        : "+f"(c[0]), "+f"(c[1]), "+f"(c[2]), "+f"(c[3])
        : "r"(a[0]), "r"(a[1]), "r"(a[2]), "r"(a[3]), "r"(b[0]), "r"(b[1]));
}

__device__ __forceinline__ void ldsm_x4(uint32_t* r, uint32_t addr) {
    asm volatile("ldmatrix.sync.aligned.m8n8.x4.shared.b16 {%0,%1,%2,%3}, [%4];"
                 : "=r"(r[0]), "=r"(r[1]), "=r"(r[2]), "=r"(r[3]) : "r"(addr));
}

__global__ void __launch_bounds__(256, 2) sage_gemm_kernel(
    const float* __restrict__ bias,
    float* __restrict__ out,
    int M, int layer, int do_relu) {
    extern __shared__ uint32_t smem[];
    uint32_t* sA = smem;                        // 2 stages x [128][T_STR]
    uint32_t* sB = smem + 2 * SA_SZ;            // 2 stages x [128][T_STR]
    const uint32_t smem_u32 = (uint32_t)__cvta_generic_to_shared(smem);

    const int tid = threadIdx.x;
    const int lane = tid & 31;
    const int wid = tid >> 5;
    const int wm = wid >> 1;          // 0..3  (m32 each)
    const int wn = wid & 1;           // 0..1  (n64 each)
    const int bm = blockIdx.y * 128;
    const int bn = blockIdx.x * 128;

    const uint32_t* Xh = layer ? g_a1_hi : g_feat_hi;
    const uint32_t* Wh = g_wth[layer];

    float acc[2][8][4] = {};

    // stage = 64 k-halves = 32 words per row; 8 chunks of 16B per row
    auto load_tile = [&](int it, int buf) {
        const uint32_t* A = (it < 4) ? Xh : (const uint32_t*)g_nhi;
        int klw = (it & 3) * 32;
        uint32_t* dA = sA + buf * SA_SZ;
        uint32_t* dB = sB + buf * SB_SZ;
#pragma unroll
        for (int i = 0; i < 4; ++i) {            // A: 128 rows x 8 chunks
            int ci = i * 256 + tid;
            int row = ci >> 3, ch = ci & 7;
            int grow = bm + row;
            bool ok = grow < M;
            size_t off = (size_t)(ok ? grow : (M - 1)) * 128 + klw + ch * 4;
            cp_async16(dA + row * T_STR + ch * 4, A + off, ok);
        }
#pragma unroll
        for (int i = 0; i < 4; ++i) {            // B: 128 rows x 8 chunks
            int ci = i * 256 + tid;
            int row = ci >> 3, ch = ci & 7;
            size_t off = (size_t)(bn + row) * 256 + it * 32 + ch * 4;
            cp_async16(dB + row * T_STR + ch * 4, Wh + off, true);
        }
    };

    load_tile(0, 0);
    asm volatile("cp.async.commit_group;" ::: "memory");

    const int a_r = wm * 32 + (lane & 15);
    const int a_w = (lane >> 4) << 2;
    const int b_r = wn * 64 + (lane & 7) + ((lane >> 4) << 3);
    const int b_w = ((lane >> 3) & 1) << 2;

    const int K_ITERS = 512 / 64;  // 8
#pragma unroll 1
    for (int it = 0; it < K_ITERS; ++it) {
        // wait current stage's loads (only group in flight), publish to all
        asm volatile("cp.async.wait_group 0;" ::: "memory");
        __syncthreads();
        // issue next stage AFTER the sync (prev compute finished before sync)
        if (it + 1 < K_ITERS) {
            load_tile(it + 1, (it + 1) & 1);
            asm volatile("cp.async.commit_group;" ::: "memory");
        }

        const uint32_t aB = smem_u32 + ((it & 1) * SA_SZ) * 4;
        const uint32_t bB = smem_u32 + (2 * SA_SZ + (it & 1) * SB_SZ) * 4;

#pragma unroll
        for (int ks = 0; ks < 4; ++ks) {
            uint32_t ah[2][4];
#pragma unroll
            for (int mt = 0; mt < 2; ++mt) {
                uint32_t off = (uint32_t)(((a_r + mt * 16) * T_STR + a_w + ks * 8) * 4);
                ldsm_x4(ah[mt], aB + off);
            }
#pragma unroll
            for (int np = 0; np < 4; ++np) {
                uint32_t off = (uint32_t)(((b_r + np * 16) * T_STR + b_w + ks * 8) * 4);
                uint32_t th[4];
                ldsm_x4(th, bB + off);
#pragma unroll
                for (int mt = 0; mt < 2; ++mt) {
                    mma_f16(acc[mt][np * 2 + 0], ah[mt], th + 0);
                    mma_f16(acc[mt][np * 2 + 1], ah[mt], th + 2);
                }
            }
        }
    }

    // ---- epilogue: bias (+relu); layer 0 also writes a1 fp16 ----
#pragma unroll
    for (int mt = 0; mt < 2; ++mt) {
        int r0 = bm + wm * 32 + mt * 16 + (lane >> 2);
#pragma unroll
        for (int nt = 0; nt < 8; ++nt) {
            int cc = bn + wn * 64 + nt * 8 + (lane & 3) * 2;
            float bx = __ldg(bias + cc);
            float by = __ldg(bias + cc + 1);
            float2 v0, v1;
            v0.x = acc[mt][nt][0] + bx; v0.y = acc[mt][nt][1] + by;
            v1.x = acc[mt][nt][2] + bx; v1.y = acc[mt][nt][3] + by;
            if (do_relu) {
                v0.x = fmaxf(v0.x, 0.f); v0.y = fmaxf(v0.y, 0.f);
                v1.x = fmaxf(v1.x, 0.f); v1.y = fmaxf(v1.y, 0.f);
            }
            if (r0 < M) {
                *(float2*)(out + (size_t)r0 * 256 + cc) = v0;
                if (do_relu)
                    g_a1_hi[(size_t)r0 * 128 + (cc >> 1)] = pack2(v0.x, v0.y);
            }
            if (r0 + 8 < M) {
                *(float2*)(out + (size_t)(r0 + 8) * 256 + cc) = v1;
                if (do_relu)
                    g_a1_hi[(size_t)(r0 + 8) * 128 + (cc >> 1)] = pack2(v1.x, v1.y);
            }
        }
    }
}

// ---------------------------------------------------------------------------
extern "C" void kernel_launch(void* const* d_in, const int* in_sizes, int n_in,
                              void* d_out, int out_size) {
    const float* feat = (const float*)d_in[0];
    const int*   src  = (const int*)d_in[1];
    const int*   dst  = (const int*)d_in[2];
    const float* Ws0  = (const float*)d_in[3];
    const float* Wn0  = (const float*)d_in[4];
    const float* b0   = (const float*)d_in[5];
    const float* Ws1  = (const float*)d_in[6];
    const float* Wn1  = (const float*)d_in[7];
    const float* b1   = (const float*)d_in[8];

    int N = in_sizes[0] / D;   // 100000
    int E = in_sizes[1];       // 1600000

    float* out0 = (float*)d_out;
    float* a1   = out0 + (size_t)N * D;
    float* h2   = out0 + 2 * (size_t)N * D;

    int nd4 = N * (D / 4);
    int nb = (N + SCAN_BLK - 1) / SCAN_BLK;

    cudaFuncSetAttribute(sage_gemm_kernel,
                         cudaFuncAttributeMaxDynamicSharedMemorySize, SMEM_BYTES);

    copy_convert_kernel<<<(nd4 + 255) / 256, 256>>>(feat, out0, nd4, N,
                                                    Ws0, Wn0, Ws1, Wn1);
    hist_kernel<<<(E + 255) / 256, 256>>>(dst, E);
    scan_blocks_kernel<<<nb, SCAN_BLK>>>(N);
    scan_add_kernel<<<(N + 255) / 256, 256>>>(N, E);
    fill_kernel<<<(E + 255) / 256, 256>>>(src, dst, E);

    gather_kernel<<<(N + 7) / 8, 256>>>(0, N);

    dim3 ggrid(2, (N + 127) / 128);

    sage_gemm_kernel<<<ggrid, 256, SMEM_BYTES>>>(b0, a1, N, 0, 1);
    gather_kernel<<<(N + 7) / 8, 256>>>(1, N);
    sage_gemm_kernel<<<ggrid, 256, SMEM_BYTES>>>(b1, h2, N, 1, 0);
}

// round 17
// speedup vs baseline: 2.3564x; 1.0009x over previous
#include <cuda_runtime.h>
#include <cuda_fp16.h>
#include <cstddef>
#include <cstdint>

#define D 256
#define N_MAX 100000
#define E_MAX 1600000
#define SCAN_BLK 1024

// R2:  NEVER pass __device__ symbols as host-side kernel args (ATS shadow -> zeros).
// R8:  harness PTX targets compute_103 (no 'a') -> tcgen05 unavailable; legacy mma only.
// R10: all kernels saturate the chip -> single stream; per-kernel efficiency only.
// R11/15/16: GEMM at legacy-HMMA floor (single-sync BK=64 pipeline).
// R12-14: fp16 precision-for-bandwidth validated (3.64e-4, 2.7x margin; floor).
// R17: CSR fused: hist inside copy_convert; g_cnt re-zeroed by scan_blocks
//      (zero-init at load + re-zero each run keeps graph replays deterministic).

// ---- scratch (__device__ globals; allocation-free rule) ----
__device__ uint32_t g_feat_hi[(size_t)N_MAX * 128];  // fp16x2 words, [row][128]
__device__ uint32_t g_a1_hi[(size_t)N_MAX * 128];
__device__ uint32_t g_nhi[(size_t)N_MAX * 128];      // neigh aggregate, fp16
__device__ uint32_t g_wth[2][256 * 256];             // W^T: [n][512k as 256 words]
__device__ int g_cnt[N_MAX];                          // zero at entry (see R17 note)
__device__ int g_off[N_MAX + 1];
__device__ int g_cursor[N_MAX];
__device__ int g_bsum[(N_MAX + SCAN_BLK - 1) / SCAN_BLK + 1];
__device__ int g_esrc[E_MAX];

// ---- fp16 helpers ----
__device__ __forceinline__ uint32_t pack2(float lo_elem, float hi_elem) {
    __half2 t = __floats2half2_rn(lo_elem, hi_elem);  // .x = low half
    return *reinterpret_cast<uint32_t*>(&t);
}
__device__ __forceinline__ void acc_word(float* a, uint32_t w) {
    float2 f = __half22float2(*reinterpret_cast<__half2*>(&w));
    a[0] += f.x; a[1] += f.y;
}

// ---------------------------------------------------------------------------
// Fused prologue: copy feat -> out[0], convert feat to fp16, transpose+convert
// both weight matrices, AND build the degree histogram (g_cnt must be zero at
// entry; re-zeroed by scan_blocks each run).
__global__ void copy_convert_kernel(const float* __restrict__ in,
                                    float* __restrict__ out, int n4, int E,
                                    const int* __restrict__ dst,
                                    const float* __restrict__ Ws0,
                                    const float* __restrict__ Wn0,
                                    const float* __restrict__ Ws1,
                                    const float* __restrict__ Wn1) {
    int i = blockIdx.x * blockDim.x + threadIdx.x;
    if (i < E) atomicAdd(&g_cnt[__ldg(dst + i)], 1);
    if (i < 2 * 256 * 256) {
        int layer = i >> 16;
        int idx = i & 65535;
        const float* Ws = layer ? Ws1 : Ws0;
        const float* Wn = layer ? Wn1 : Wn0;
        int n = idx & 255;
        int wp = idx >> 8;
        int k0 = wp * 2, k1 = k0 + 1;
        float v0 = (k0 < 256) ? Ws[k0 * 256 + n] : Wn[(k0 - 256) * 256 + n];
        float v1 = (k1 < 256) ? Ws[k1 * 256 + n] : Wn[(k1 - 256) * 256 + n];
        g_wth[layer][n * 256 + wp] = pack2(v0, v1);
    }
    if (i >= n4) return;
    float4 v = ((const float4*)in)[i];
    ((float4*)out)[i] = v;
    *(uint2*)&g_feat_hi[(size_t)i * 2] =
        make_uint2(pack2(v.x, v.y), pack2(v.z, v.w));
}

// Block-level exclusive scan; also RE-ZEROES g_cnt for the next run/replay.
__global__ void scan_blocks_kernel(int n) {
    __shared__ int sm[SCAN_BLK];
    int tid = threadIdx.x;
    int i = blockIdx.x * SCAN_BLK + tid;
    int v = 0;
    if (i < n) {
        v = g_cnt[i];
        g_cnt[i] = 0;          // reset for next graph replay
    }
    sm[tid] = v;
    __syncthreads();
#pragma unroll
    for (int off = 1; off < SCAN_BLK; off <<= 1) {
        int t = (tid >= off) ? sm[tid - off] : 0;
        __syncthreads();
        sm[tid] += t;
        __syncthreads();
    }
    if (i < n) g_off[i] = sm[tid] - v;
    if (tid == SCAN_BLK - 1) g_bsum[blockIdx.x] = sm[tid];
}

__global__ void scan_add_kernel(int n, int E) {
    __shared__ int pref;
    int g = (blockIdx.x * 256) >> 10;
    if (threadIdx.x < 32) {
        int s = 0;
        for (int j = threadIdx.x; j < g; j += 32) s += g_bsum[j];
#pragma unroll
        for (int o = 16; o; o >>= 1) s += __shfl_down_sync(0xFFFFFFFFu, s, o);
        if (threadIdx.x == 0) pref = s;
    }
    __syncthreads();
    int i = blockIdx.x * 256 + threadIdx.x;
    if (i < n) {
        int v = g_off[i] + pref;
        g_off[i] = v;
        g_cursor[i] = v;
    }
    if (i == 0) g_off[n] = E;
}

__global__ void fill_kernel(const int* __restrict__ src,
                            const int* __restrict__ dst, int E) {
    int e = blockIdx.x * blockDim.x + threadIdx.x;
    if (e < E) {
        int d = dst[e];
        int p = atomicAdd(&g_cursor[d], 1);
        g_esrc[p] = src[e];
    }
}

// ---------------------------------------------------------------------------
// Gather from fp16 rows (512B/edge): one warp per dst node, lane covers 8
// elems (one uint4). fp32 accumulate, fp16 output. layer selects DEVICE symbol.
__global__ void gather_kernel(int layer, int N) {
    int node = blockIdx.x * 8 + (threadIdx.x >> 5);
    if (node >= N) return;
    int lane = threadIdx.x & 31;

    const uint32_t* Xh = layer ? g_a1_hi : g_feat_hi;

    int beg = g_off[node];
    int end = g_off[node + 1];

    float a[8] = {};

    int i = beg;
    for (; i + 3 < end; i += 4) {
        int s0 = __ldg(g_esrc + i);
        int s1 = __ldg(g_esrc + i + 1);
        int s2 = __ldg(g_esrc + i + 2);
        int s3 = __ldg(g_esrc + i + 3);
        uint4 w0 = __ldg((const uint4*)(Xh + (size_t)s0 * 128) + lane);
        uint4 w1 = __ldg((const uint4*)(Xh + (size_t)s1 * 128) + lane);
        uint4 w2 = __ldg((const uint4*)(Xh + (size_t)s2 * 128) + lane);
        uint4 w3 = __ldg((const uint4*)(Xh + (size_t)s3 * 128) + lane);
        acc_word(a + 0, w0.x); acc_word(a + 2, w0.y);
        acc_word(a + 4, w0.z); acc_word(a + 6, w0.w);
        acc_word(a + 0, w1.x); acc_word(a + 2, w1.y);
        acc_word(a + 4, w1.z); acc_word(a + 6, w1.w);
        acc_word(a + 0, w2.x); acc_word(a + 2, w2.y);
        acc_word(a + 4, w2.z); acc_word(a + 6, w2.w);
        acc_word(a + 0, w3.x); acc_word(a + 2, w3.y);
        acc_word(a + 4, w3.z); acc_word(a + 6, w3.w);
    }
    for (; i < end; ++i) {
        int s0 = __ldg(g_esrc + i);
        uint4 w0 = __ldg((const uint4*)(Xh + (size_t)s0 * 128) + lane);
        acc_word(a + 0, w0.x); acc_word(a + 2, w0.y);
        acc_word(a + 4, w0.z); acc_word(a + 6, w0.w);
    }

    float inv = (end > beg) ? (1.0f / (float)(end - beg)) : 0.f;
    uint4 ow;
    ow.x = pack2(a[0] * inv, a[1] * inv);
    ow.y = pack2(a[2] * inv, a[3] * inv);
    ow.z = pack2(a[4] * inv, a[5] * inv);
    ow.w = pack2(a[6] * inv, a[7] * inv);
    *((uint4*)(g_nhi + (size_t)node * 128) + lane) = ow;
}

// ---------------------------------------------------------------------------
// fp16 tensor GEMM: out[M,256] = [Xh | NH] @ Wt^T + bias, fp32 accum.
// CTA 128x128, warp 32x64, BK=64 stages, one __syncthreads per iteration.
#define T_STR 36
#define SA_SZ (128 * T_STR)
#define SB_SZ (128 * T_STR)
#define SMEM_WORDS (2 * (SA_SZ + SB_SZ))
#define SMEM_BYTES (SMEM_WORDS * 4)

__device__ __forceinline__ void cp_async16(void* s, const void* g, bool pred) {
    uint32_t sa = (uint32_t)__cvta_generic_to_shared(s);
    int sz = pred ? 16 : 0;
    asm volatile("cp.async.cg.shared.global [%0], [%1], 16, %2;"
                 :: "r"(sa), "l"(g), "r"(sz) : "memory");
}

__device__ __forceinline__ void mma_f16(float* c, const uint32_t* a, const uint32_t* b) {
    asm volatile(
        "mma.sync.aligned.m16n8k16.row.col.f32.f16.f16.f32 "
        "{%0,%1,%2,%3}, {%4,%5,%6,%7}, {%8,%9}, {%0,%1,%2,%3};"
        : "+f"(c[0]), "+f"(c[1]), "+f"(c[2]), "+f"(c[3])
        : "r"(a[0]), "r"(a[1]), "r"(a[2]), "r"(a[3]), "r"(b[0]), "r"(b[1]));
}

__device__ __forceinline__ void ldsm_x4(uint32_t* r, uint32_t addr) {
    asm volatile("ldmatrix.sync.aligned.m8n8.x4.shared.b16 {%0,%1,%2,%3}, [%4];"
                 : "=r"(r[0]), "=r"(r[1]), "=r"(r[2]), "=r"(r[3]) : "r"(addr));
}

__global__ void __launch_bounds__(256, 2) sage_gemm_kernel(
    const float* __restrict__ bias,
    float* __restrict__ out,
    int M, int layer, int do_relu) {
    extern __shared__ uint32_t smem[];
    uint32_t* sA = smem;                        // 2 stages x [128][T_STR]
    uint32_t* sB = smem + 2 * SA_SZ;            // 2 stages x [128][T_STR]
    const uint32_t smem_u32 = (uint32_t)__cvta_generic_to_shared(smem);

    const int tid = threadIdx.x;
    const int lane = tid & 31;
    const int wid = tid >> 5;
    const int wm = wid >> 1;          // 0..3  (m32 each)
    const int wn = wid & 1;           // 0..1  (n64 each)
    const int bm = blockIdx.y * 128;
    const int bn = blockIdx.x * 128;

    const uint32_t* Xh = layer ? g_a1_hi : g_feat_hi;
    const uint32_t* Wh = g_wth[layer];

    float acc[2][8][4] = {};

    auto load_tile = [&](int it, int buf) {
        const uint32_t* A = (it < 4) ? Xh : (const uint32_t*)g_nhi;
        int klw = (it & 3) * 32;
        uint32_t* dA = sA + buf * SA_SZ;
        uint32_t* dB = sB + buf * SB_SZ;
#pragma unroll
        for (int i = 0; i < 4; ++i) {            // A: 128 rows x 8 chunks
            int ci = i * 256 + tid;
            int row = ci >> 3, ch = ci & 7;
            int grow = bm + row;
            bool ok = grow < M;
            size_t off = (size_t)(ok ? grow : (M - 1)) * 128 + klw + ch * 4;
            cp_async16(dA + row * T_STR + ch * 4, A + off, ok);
        }
#pragma unroll
        for (int i = 0; i < 4; ++i) {            // B: 128 rows x 8 chunks
            int ci = i * 256 + tid;
            int row = ci >> 3, ch = ci & 7;
            size_t off = (size_t)(bn + row) * 256 + it * 32 + ch * 4;
            cp_async16(dB + row * T_STR + ch * 4, Wh + off, true);
        }
    };

    load_tile(0, 0);
    asm volatile("cp.async.commit_group;" ::: "memory");

    const int a_r = wm * 32 + (lane & 15);
    const int a_w = (lane >> 4) << 2;
    const int b_r = wn * 64 + (lane & 7) + ((lane >> 4) << 3);
    const int b_w = ((lane >> 3) & 1) << 2;

    const int K_ITERS = 512 / 64;  // 8
#pragma unroll 1
    for (int it = 0; it < K_ITERS; ++it) {
        asm volatile("cp.async.wait_group 0;" ::: "memory");
        __syncthreads();
        if (it + 1 < K_ITERS) {
            load_tile(it + 1, (it + 1) & 1);
            asm volatile("cp.async.commit_group;" ::: "memory");
        }

        const uint32_t aB = smem_u32 + ((it & 1) * SA_SZ) * 4;
        const uint32_t bB = smem_u32 + (2 * SA_SZ + (it & 1) * SB_SZ) * 4;

#pragma unroll
        for (int ks = 0; ks < 4; ++ks) {
            uint32_t ah[2][4];
#pragma unroll
            for (int mt = 0; mt < 2; ++mt) {
                uint32_t off = (uint32_t)(((a_r + mt * 16) * T_STR + a_w + ks * 8) * 4);
                ldsm_x4(ah[mt], aB + off);
            }
#pragma unroll
            for (int np = 0; np < 4; ++np) {
                uint32_t off = (uint32_t)(((b_r + np * 16) * T_STR + b_w + ks * 8) * 4);
                uint32_t th[4];
                ldsm_x4(th, bB + off);
#pragma unroll
                for (int mt = 0; mt < 2; ++mt) {
                    mma_f16(acc[mt][np * 2 + 0], ah[mt], th + 0);
                    mma_f16(acc[mt][np * 2 + 1], ah[mt], th + 2);
                }
            }
        }
    }

    // ---- epilogue: bias (+relu); layer 0 also writes a1 fp16 ----
#pragma unroll
    for (int mt = 0; mt < 2; ++mt) {
        int r0 = bm + wm * 32 + mt * 16 + (lane >> 2);
#pragma unroll
        for (int nt = 0; nt < 8; ++nt) {
            int cc = bn + wn * 64 + nt * 8 + (lane & 3) * 2;
            float bx = __ldg(bias + cc);
            float by = __ldg(bias + cc + 1);
            float2 v0, v1;
            v0.x = acc[mt][nt][0] + bx; v0.y = acc[mt][nt][1] + by;
            v1.x = acc[mt][nt][2] + bx; v1.y = acc[mt][nt][3] + by;
            if (do_relu) {
                v0.x = fmaxf(v0.x, 0.f); v0.y = fmaxf(v0.y, 0.f);
                v1.x = fmaxf(v1.x, 0.f); v1.y = fmaxf(v1.y, 0.f);
            }
            if (r0 < M) {
                *(float2*)(out + (size_t)r0 * 256 + cc) = v0;
                if (do_relu)
                    g_a1_hi[(size_t)r0 * 128 + (cc >> 1)] = pack2(v0.x, v0.y);
            }
            if (r0 + 8 < M) {
                *(float2*)(out + (size_t)(r0 + 8) * 256 + cc) = v1;
                if (do_relu)
                    g_a1_hi[(size_t)(r0 + 8) * 128 + (cc >> 1)] = pack2(v1.x, v1.y);
            }
        }
    }
}

// ---------------------------------------------------------------------------
extern "C" void kernel_launch(void* const* d_in, const int* in_sizes, int n_in,
                              void* d_out, int out_size) {
    const float* feat = (const float*)d_in[0];
    const int*   src  = (const int*)d_in[1];
    const int*   dst  = (const int*)d_in[2];
    const float* Ws0  = (const float*)d_in[3];
    const float* Wn0  = (const float*)d_in[4];
    const float* b0   = (const float*)d_in[5];
    const float* Ws1  = (const float*)d_in[6];
    const float* Wn1  = (const float*)d_in[7];
    const float* b1   = (const float*)d_in[8];

    int N = in_sizes[0] / D;   // 100000
    int E = in_sizes[1];       // 1600000

    float* out0 = (float*)d_out;
    float* a1   = out0 + (size_t)N * D;
    float* h2   = out0 + 2 * (size_t)N * D;

    int nd4 = N * (D / 4);
    int nb = (N + SCAN_BLK - 1) / SCAN_BLK;

    cudaFuncSetAttribute(sage_gemm_kernel,
                         cudaFuncAttributeMaxDynamicSharedMemorySize, SMEM_BYTES);

    // 1: copy + fp16 convert + weight convert + degree histogram
    copy_convert_kernel<<<(nd4 + 255) / 256, 256>>>(feat, out0, nd4, E, dst,
                                                    Ws0, Wn0, Ws1, Wn1);
    // 2-4: scan (+cnt re-zero) and CSR fill
    scan_blocks_kernel<<<nb, SCAN_BLK>>>(N);
    scan_add_kernel<<<(N + 255) / 256, 256>>>(N, E);
    fill_kernel<<<(E + 255) / 256, 256>>>(src, dst, E);

    dim3 ggrid(2, (N + 127) / 128);

    // 5-8: layer pipeline
    gather_kernel<<<(N + 7) / 8, 256>>>(0, N);
    sage_gemm_kernel<<<ggrid, 256, SMEM_BYTES>>>(b0, a1, N, 0, 1);
    gather_kernel<<<(N + 7) / 8, 256>>>(1, N);
    sage_gemm_kernel<<<ggrid, 256, SMEM_BYTES>>>(b1, h2, N, 1, 0);
}